// round 12
// baseline (speedup 1.0000x reference)
#include <cuda_runtime.h>
#include <cuda_bf16.h>
#include <cstdint>
#include <cstddef>

// Problem constants
constexpr int SEQ   = 1024;
constexpr int HIDC  = 1024;
constexpr int NHC   = 32;
constexpr int HDC   = 32;
constexpr int BATCH = 4;
constexpr int MR    = BATCH * SEQ;   // 4096 rows
constexpr int WR    = HIDC / 2;      // 512 words per row

// Scratch (R8 set)
__device__ float g_q[(size_t)MR * HIDC];
__device__ float g_k[(size_t)MR * HIDC];
__device__ float g_v[(size_t)MR * HIDC];
__device__ float g_ctx[(size_t)MR * HIDC];
__device__ float g_x[(size_t)MR * HIDC];

// Pre-converted bf16 hi/lo words (hidden + Wq/Wk/Wv)
__device__ uint32_t g_hh[(size_t)MR * WR],       g_hl[(size_t)MR * WR];
__device__ uint32_t g_wh[(size_t)3 * HIDC * WR], g_wl[(size_t)3 * HIDC * WR];

__device__ __forceinline__ uint32_t f2tf32(float x) {
    uint32_t r;
    asm("cvt.rna.tf32.f32 %0, %1;" : "=r"(r) : "f"(x));
    return r;
}

__device__ __forceinline__ void mma_tf32(float* c, const uint32_t* a, const uint32_t* b) {
    asm volatile(
        "mma.sync.aligned.m16n8k8.row.col.f32.tf32.tf32.f32 "
        "{%0,%1,%2,%3}, {%4,%5,%6,%7}, {%8,%9}, {%0,%1,%2,%3};\n"
        : "+f"(c[0]), "+f"(c[1]), "+f"(c[2]), "+f"(c[3])
        : "r"(a[0]), "r"(a[1]), "r"(a[2]), "r"(a[3]), "r"(b[0]), "r"(b[1]));
}

__device__ __forceinline__ void mma_bf16(float* c, const uint32_t* a, const uint32_t* b) {
    asm volatile(
        "mma.sync.aligned.m16n8k16.row.col.f32.bf16.bf16.f32 "
        "{%0,%1,%2,%3}, {%4,%5,%6,%7}, {%8,%9}, {%0,%1,%2,%3};\n"
        : "+f"(c[0]), "+f"(c[1]), "+f"(c[2]), "+f"(c[3])
        : "r"(a[0]), "r"(a[1]), "r"(a[2]), "r"(a[3]), "r"(b[0]), "r"(b[1]));
}

// Split f32 pair -> bf16x2 hi word + bf16x2 residual word.
__device__ __forceinline__ void cvt_pair(float x, float y, uint32_t& hi, uint32_t& lo) {
    __nv_bfloat162 h = __float22bfloat162_rn(make_float2(x, y));
    float2 hf = __bfloat1622float2(h);
    __nv_bfloat162 l = __float22bfloat162_rn(make_float2(x - hf.x, y - hf.y));
    hi = *reinterpret_cast<uint32_t*>(&h);
    lo = *reinterpret_cast<uint32_t*>(&l);
}

// ---------------------------------------------------------------------------
// Prepass: fp32 -> bf16 hi/lo word pairs.
// Destination selected by `which` and resolved IN DEVICE CODE — __device__
// symbols must never be passed as kernel arguments from host (host shadow
// address; silently writes host memory on GB300 ATS).
// ---------------------------------------------------------------------------
__global__ void cvt_kernel(const float* __restrict__ src, int which, int nwords)
{
    uint32_t* dh;
    uint32_t* dl;
    const size_t WW = (size_t)HIDC * WR;
    if (which == 0)      { dh = g_hh;           dl = g_hl; }
    else if (which == 1) { dh = g_wh;           dl = g_wl; }
    else if (which == 2) { dh = g_wh + WW;      dl = g_wl + WW; }
    else                 { dh = g_wh + 2 * WW;  dl = g_wl + 2 * WW; }

    const int i = blockIdx.x * blockDim.x + threadIdx.x;  // word-pair index
    if (2 * i < nwords) {
        float4 v = ((const float4*)src)[i];
        uint32_t h0, l0, h1, l1;
        cvt_pair(v.x, v.y, h0, l0);
        cvt_pair(v.z, v.w, h1, l1);
        *(uint2*)&dh[2 * i] = make_uint2(h0, h1);
        *(uint2*)&dl[2 * i] = make_uint2(l0, l1);
    }
}

constexpr int LDB = 12;

// ---------------------------------------------------------------------------
// Word-input GEMM (qkv): A/B pre-converted bf16 hi/lo words; C fp32 + bias.
// CTA tile 128x128x16 (8 k-words), 8 warps (2M x 4N), 2-stage ping-pong.
// ---------------------------------------------------------------------------
__global__ __launch_bounds__(256, 2) void qkv_gemm(
    const float* __restrict__ bq, const float* __restrict__ bk,
    const float* __restrict__ bv)
{
    __shared__ uint32_t sAh[2][128 * LDB], sAl[2][128 * LDB];
    __shared__ uint32_t sBh[2][128 * LDB], sBl[2][128 * LDB];

    const size_t ws = (size_t)blockIdx.z * HIDC * WR;
    const uint32_t* Bh = g_wh + ws;
    const uint32_t* Bl = g_wl + ws;
    const float* bias;
    float* C;
    if (blockIdx.z == 0)      { bias = bq; C = g_q; }
    else if (blockIdx.z == 1) { bias = bk; C = g_k; }
    else                      { bias = bv; C = g_v; }

    const int t    = threadIdx.x;
    const int m0   = blockIdx.y * 128;
    const int n0   = blockIdx.x * 128;
    const int wid  = t >> 5, lane = t & 31;
    const int wm   = wid & 1, wn = wid >> 1;
    const int g    = lane >> 2, t4 = lane & 3;

    const int lr = t >> 1;             // 0..127
    const int wq = (t & 1) * 4;        // 0 or 4
    const uint32_t* Aph = g_hh + (size_t)(m0 + lr) * WR + wq;
    const uint32_t* Apl = g_hl + (size_t)(m0 + lr) * WR + wq;
    const uint32_t* Bph = Bh + (size_t)(n0 + lr) * WR + wq;
    const uint32_t* Bpl = Bl + (size_t)(n0 + lr) * WR + wq;

    float acc[4][4][4];
#pragma unroll
    for (int i = 0; i < 4; i++)
#pragma unroll
        for (int j = 0; j < 4; j++)
#pragma unroll
            for (int r = 0; r < 4; r++) acc[i][j][r] = 0.f;

    uint4 pa_h, pa_l, pb_h, pb_l;
    auto gload = [&](int kt) {
        pa_h = *(const uint4*)(Aph + kt * 8);
        pa_l = *(const uint4*)(Apl + kt * 8);
        pb_h = *(const uint4*)(Bph + kt * 8);
        pb_l = *(const uint4*)(Bpl + kt * 8);
    };
    auto sts = [&](int st) {
        *(uint4*)&sAh[st][lr * LDB + wq] = pa_h;
        *(uint4*)&sAl[st][lr * LDB + wq] = pa_l;
        *(uint4*)&sBh[st][lr * LDB + wq] = pb_h;
        *(uint4*)&sBl[st][lr * LDB + wq] = pb_l;
    };

    gload(0);
    sts(0);
    __syncthreads();

    constexpr int NKT = WR / 8;  // 64 k-tiles
    for (int kt = 0; kt < NKT; kt++) {
        const int st = kt & 1;
        if (kt + 1 < NKT) gload(kt + 1);

        uint32_t bh[4][2], bl[4][2];
#pragma unroll
        for (int nf = 0; nf < 4; nf++) {
            const int n = (wn * 32 + nf * 8 + g) * LDB;
            bh[nf][0] = sBh[st][n + t4];
            bh[nf][1] = sBh[st][n + t4 + 4];
            bl[nf][0] = sBl[st][n + t4];
            bl[nf][1] = sBl[st][n + t4 + 4];
        }
#pragma unroll
        for (int mf = 0; mf < 4; mf++) {
            const int m = (wm * 64 + mf * 16 + g) * LDB;
            uint32_t ah[4], al[4];
            ah[0] = sAh[st][m + t4];
            ah[1] = sAh[st][m + 8 * LDB + t4];
            ah[2] = sAh[st][m + t4 + 4];
            ah[3] = sAh[st][m + 8 * LDB + t4 + 4];
            al[0] = sAl[st][m + t4];
            al[1] = sAl[st][m + 8 * LDB + t4];
            al[2] = sAl[st][m + t4 + 4];
            al[3] = sAl[st][m + 8 * LDB + t4 + 4];
#pragma unroll
            for (int nf = 0; nf < 4; nf++) {
                mma_bf16(acc[mf][nf], ah, bh[nf]);
                mma_bf16(acc[mf][nf], ah, bl[nf]);
                mma_bf16(acc[mf][nf], al, bh[nf]);
            }
        }

        if (kt + 1 < NKT) {
            sts((kt + 1) & 1);
            __syncthreads();
        }
    }

#pragma unroll
    for (int mf = 0; mf < 4; mf++) {
#pragma unroll
        for (int nf = 0; nf < 4; nf++) {
            const int row = m0 + wm * 64 + mf * 16 + g;
            const int col = n0 + wn * 32 + nf * 8 + t4 * 2;
            float2 bb = *(const float2*)(bias + col);
            float2 o0, o1;
            o0.x = acc[mf][nf][0] + bb.x;
            o0.y = acc[mf][nf][1] + bb.y;
            o1.x = acc[mf][nf][2] + bb.x;
            o1.y = acc[mf][nf][3] + bb.y;
            *(float2*)(C + (size_t)row * HIDC + col)       = o0;
            *(float2*)(C + (size_t)(row + 8) * HIDC + col) = o1;
        }
    }
}

// ---------------------------------------------------------------------------
// R8 fp32-staging GEMM body (verbatim) — used for o_gemm only.
// ---------------------------------------------------------------------------
__device__ __forceinline__ void gemm_tc_body(const float* __restrict__ A,
                                             const float* __restrict__ B,
                                             const float* __restrict__ bias,
                                             const float* __restrict__ resid,
                                             float* __restrict__ C)
{
    __shared__ uint32_t sAh[2][128 * LDB], sAl[2][128 * LDB];
    __shared__ uint32_t sBh[2][128 * LDB], sBl[2][128 * LDB];

    const int t    = threadIdx.x;
    const int m0   = blockIdx.y * 128;
    const int n0   = blockIdx.x * 128;
    const int wid  = t >> 5, lane = t & 31;
    const int wm   = wid & 1, wn = wid >> 1;
    const int g    = lane >> 2, t4 = lane & 3;

    const int lr = t >> 2;             // 0..63
    const int lw = (t & 3) * 2;        // word offset 0,2,4,6
    const float* Ap = A + (size_t)(m0 + lr) * HIDC + (t & 3) * 4;
    const float* Bp = B + (size_t)(n0 + lr) * HIDC + (t & 3) * 4;

    float acc[4][4][4];
#pragma unroll
    for (int i = 0; i < 4; i++)
#pragma unroll
        for (int j = 0; j < 4; j++)
#pragma unroll
            for (int r = 0; r < 4; r++) acc[i][j][r] = 0.f;

    float4 ra0, ra1, rb0, rb1;
    auto gload = [&](int kt) {
        const float* a = Ap + kt * 16;
        const float* b = Bp + kt * 16;
        ra0 = *(const float4*)(a);
        ra1 = *(const float4*)(a + (size_t)64 * HIDC);
        rb0 = *(const float4*)(b);
        rb1 = *(const float4*)(b + (size_t)64 * HIDC);
    };
    auto sts = [&](int st) {
        uint32_t h0, l0, h1, l1;
        cvt_pair(ra0.x, ra0.y, h0, l0); cvt_pair(ra0.z, ra0.w, h1, l1);
        sAh[st][lr * LDB + lw] = h0; sAh[st][lr * LDB + lw + 1] = h1;
        sAl[st][lr * LDB + lw] = l0; sAl[st][lr * LDB + lw + 1] = l1;
        cvt_pair(ra1.x, ra1.y, h0, l0); cvt_pair(ra1.z, ra1.w, h1, l1);
        sAh[st][(lr + 64) * LDB + lw] = h0; sAh[st][(lr + 64) * LDB + lw + 1] = h1;
        sAl[st][(lr + 64) * LDB + lw] = l0; sAl[st][(lr + 64) * LDB + lw + 1] = l1;
        cvt_pair(rb0.x, rb0.y, h0, l0); cvt_pair(rb0.z, rb0.w, h1, l1);
        sBh[st][lr * LDB + lw] = h0; sBh[st][lr * LDB + lw + 1] = h1;
        sBl[st][lr * LDB + lw] = l0; sBl[st][lr * LDB + lw + 1] = l1;
        cvt_pair(rb1.x, rb1.y, h0, l0); cvt_pair(rb1.z, rb1.w, h1, l1);
        sBh[st][(lr + 64) * LDB + lw] = h0; sBh[st][(lr + 64) * LDB + lw + 1] = h1;
        sBl[st][(lr + 64) * LDB + lw] = l0; sBl[st][(lr + 64) * LDB + lw + 1] = l1;
    };

    gload(0);
    sts(0);
    __syncthreads();

    for (int kt = 0; kt < HIDC / 16; kt++) {
        const int st = kt & 1;
        if (kt + 1 < HIDC / 16) gload(kt + 1);

        uint32_t bh[4][2], bl[4][2];
#pragma unroll
        for (int nf = 0; nf < 4; nf++) {
            const int n = (wn * 32 + nf * 8 + g) * LDB;
            bh[nf][0] = sBh[st][n + t4];
            bh[nf][1] = sBh[st][n + t4 + 4];
            bl[nf][0] = sBl[st][n + t4];
            bl[nf][1] = sBl[st][n + t4 + 4];
        }
#pragma unroll
        for (int mf = 0; mf < 4; mf++) {
            const int m = (wm * 64 + mf * 16 + g) * LDB;
            uint32_t ah[4], al[4];
            ah[0] = sAh[st][m + t4];
            ah[1] = sAh[st][m + 8 * LDB + t4];
            ah[2] = sAh[st][m + t4 + 4];
            ah[3] = sAh[st][m + 8 * LDB + t4 + 4];
            al[0] = sAl[st][m + t4];
            al[1] = sAl[st][m + 8 * LDB + t4];
            al[2] = sAl[st][m + t4 + 4];
            al[3] = sAl[st][m + 8 * LDB + t4 + 4];
#pragma unroll
            for (int nf = 0; nf < 4; nf++) {
                mma_bf16(acc[mf][nf], ah, bh[nf]);
                mma_bf16(acc[mf][nf], ah, bl[nf]);
                mma_bf16(acc[mf][nf], al, bh[nf]);
            }
        }

        if (kt + 1 < HIDC / 16) {
            sts((kt + 1) & 1);
            __syncthreads();
        }
    }

#pragma unroll
    for (int mf = 0; mf < 4; mf++) {
#pragma unroll
        for (int nf = 0; nf < 4; nf++) {
            const int row = m0 + wm * 64 + mf * 16 + g;
            const int col = n0 + wn * 32 + nf * 8 + t4 * 2;
            float2 bb = *(const float2*)(bias + col);
            float2 o0, o1;
            o0.x = acc[mf][nf][0] + bb.x;
            o0.y = acc[mf][nf][1] + bb.y;
            o1.x = acc[mf][nf][2] + bb.x;
            o1.y = acc[mf][nf][3] + bb.y;
            if (resid != nullptr) {
                float2 r0 = *(const float2*)(resid + (size_t)row * HIDC + col);
                float2 r1 = *(const float2*)(resid + (size_t)(row + 8) * HIDC + col);
                o0.x += r0.x; o0.y += r0.y;
                o1.x += r1.x; o1.y += r1.y;
            }
            *(float2*)(C + (size_t)row * HIDC + col)       = o0;
            *(float2*)(C + (size_t)(row + 8) * HIDC + col) = o1;
        }
    }
}

__global__ __launch_bounds__(256, 2) void o_gemm(const float* __restrict__ Wo,
    const float* __restrict__ bo, const float* __restrict__ H)
{
    gemm_tc_body(g_ctx, Wo, bo, H, g_x);
}

// ---------------------------------------------------------------------------
// R8 attention — verbatim.
//  Phase 1: S = (Q K^T + bias)/sqrt(32) via 3xBF16 m16n8k16
//  Phase 2: exact softmax; write probs; normalized P back to S
//  Phase 3: ctx^T = V^T P^T via 3xTF32 m16n8k8
// ---------------------------------------------------------------------------
constexpr int SST  = 1032;  // S row stride (floats)
constexpr int KSTB = 20;    // phase-1 bf16 row stride (words; 16 used)
constexpr int KST  = 33;    // phase-3 tf32 row stride (words)

constexpr int OFF_S  = 0;
constexpr int OFF_KH = 33024;
constexpr int OFF_KL = OFF_KH + 8448;
constexpr int OFF_QH = OFF_KL + 8448;
constexpr int OFF_QL = OFF_QH + 1056;
constexpr int OFF_BS = OFF_QL + 1056;
constexpr int ATTN_FLOATS = OFF_BS + 1056;  // 53088
constexpr size_t ATTN_SMEM_BYTES = (size_t)ATTN_FLOATS * sizeof(float);

__global__ __launch_bounds__(256, 1) void attn_kernel(const float* __restrict__ dist_emb,
                                                      float* __restrict__ probs_out)
{
    extern __shared__ float sm[];
    float*    S  = sm + OFF_S;
    uint32_t* kh = (uint32_t*)(sm + OFF_KH);
    uint32_t* kl = (uint32_t*)(sm + OFF_KL);
    uint32_t* qh = (uint32_t*)(sm + OFF_QH);
    uint32_t* ql = (uint32_t*)(sm + OFF_QL);
    float*    bs = sm + OFF_BS;

    const int t   = threadIdx.x;
    const int q0  = blockIdx.x * 32;
    const int h   = blockIdx.y;
    const int b   = blockIdx.z;
    const int wid = t >> 5, lane = t & 31;
    const int g   = lane >> 2, t4 = lane & 3;

    const size_t bh_off = (size_t)b * SEQ * HIDC + (size_t)h * HDC;
    const float* Qb = g_q + bh_off;
    const float* Kb = g_k + bh_off;
    const float* Vb = g_v + bh_off;

    for (int r = t; r < 1055; r += 256)
        bs[r] = dist_emb[(size_t)(q0 + r) * HDC + h];

    // stage Q tile (32x32) as bf16 hi/lo pair-words
    {
        const int row = t >> 3, c4 = (t & 7) * 4, w2 = (t & 7) * 2;
        float4 v = *(const float4*)(Qb + (size_t)(q0 + row) * HIDC + c4);
        uint32_t h0, l0, h1, l1;
        cvt_pair(v.x, v.y, h0, l0);
        cvt_pair(v.z, v.w, h1, l1);
        qh[row * KSTB + w2]     = h0;
        qh[row * KSTB + w2 + 1] = h1;
        ql[row * KSTB + w2]     = l0;
        ql[row * KSTB + w2 + 1] = l1;
    }
    __syncthreads();

    uint32_t qfh[2][2][4], qfl[2][2][4];
#pragma unroll
    for (int mf = 0; mf < 2; mf++)
#pragma unroll
        for (int ks = 0; ks < 2; ks++) {
            const int r0 = (mf * 16 + g) * KSTB;
            const int r1 = r0 + 8 * KSTB;
            const int k0 = ks * 8 + t4;
            qfh[mf][ks][0] = qh[r0 + k0];
            qfh[mf][ks][1] = qh[r1 + k0];
            qfh[mf][ks][2] = qh[r0 + k0 + 4];
            qfh[mf][ks][3] = qh[r1 + k0 + 4];
            qfl[mf][ks][0] = ql[r0 + k0];
            qfl[mf][ks][1] = ql[r1 + k0];
            qfl[mf][ks][2] = ql[r0 + k0 + 4];
            qfl[mf][ks][3] = ql[r1 + k0 + 4];
        }

    const float scale = 0.17677669529663688f;

    // ---- Phase 1 ----
    for (int c = 0; c < 4; c++) {
        __syncthreads();
#pragma unroll
        for (int p = 0; p < 8; p++) {
            const int row = p * 32 + (t >> 3), c4 = (t & 7) * 4, w2 = (t & 7) * 2;
            float4 v = *(const float4*)(Kb + (size_t)(c * 256 + row) * HIDC + c4);
            uint32_t h0, l0, h1, l1;
            cvt_pair(v.x, v.y, h0, l0);
            cvt_pair(v.z, v.w, h1, l1);
            kh[row * KSTB + w2]     = h0;
            kh[row * KSTB + w2 + 1] = h1;
            kl[row * KSTB + w2]     = l0;
            kl[row * KSTB + w2 + 1] = l1;
        }
        __syncthreads();

        const int kw = wid * 32;
#pragma unroll
        for (int nf = 0; nf < 4; nf++) {
            uint32_t bhh[2][2], bll[2][2];
#pragma unroll
            for (int ks = 0; ks < 2; ks++) {
                const int n = (kw + nf * 8 + g) * KSTB + ks * 8 + t4;
                bhh[ks][0] = kh[n]; bhh[ks][1] = kh[n + 4];
                bll[ks][0] = kl[n]; bll[ks][1] = kl[n + 4];
            }
#pragma unroll
            for (int mf = 0; mf < 2; mf++) {
                float acc[4] = {0.f, 0.f, 0.f, 0.f};
#pragma unroll
                for (int ks = 0; ks < 2; ks++) {
                    mma_bf16(acc, qfh[mf][ks], bhh[ks]);
                    mma_bf16(acc, qfh[mf][ks], bll[ks]);
                    mma_bf16(acc, qfl[mf][ks], bhh[ks]);
                }
                const int row0 = mf * 16 + g;
                const int row1 = row0 + 8;
                const int col  = c * 256 + kw + nf * 8 + 2 * t4;
                float2 s0, s1;
                s0.x = (acc[0] + bs[row0 - col + 1023]) * scale;
                s0.y = (acc[1] + bs[row0 - col + 1022]) * scale;
                s1.x = (acc[2] + bs[row1 - col + 1023]) * scale;
                s1.y = (acc[3] + bs[row1 - col + 1022]) * scale;
                *(float2*)&S[row0 * SST + col] = s0;
                *(float2*)&S[row1 * SST + col] = s1;
            }
        }
    }
    __syncthreads();

    // ---- Phase 2 ----
    {
        float* pb = probs_out + ((size_t)(b * NHC + h) * SEQ + q0) * SEQ;
        for (int rr = 0; rr < 4; rr++) {
            const int r = wid + 8 * rr;
            float* row = S + r * SST;
            float mx = -1e30f;
            for (int i = lane; i < 1024; i += 32) mx = fmaxf(mx, row[i]);
#pragma unroll
            for (int o = 16; o > 0; o >>= 1)
                mx = fmaxf(mx, __shfl_xor_sync(0xffffffffu, mx, o));
            float sum = 0.f;
            for (int i = lane; i < 1024; i += 32) {
                float e = __expf(row[i] - mx);
                row[i] = e;
                sum += e;
            }
#pragma unroll
            for (int o = 16; o > 0; o >>= 1)
                sum += __shfl_xor_sync(0xffffffffu, sum, o);
            const float inv = 1.f / sum;
            float* pr = pb + (size_t)r * SEQ;
            for (int i = lane; i < 1024; i += 32) {
                float p = row[i] * inv;
                row[i] = p;
                pr[i]  = p;
            }
        }
    }

    // ---- Phase 3 ----
    float acc[2][4][4];
#pragma unroll
    for (int mf = 0; mf < 2; mf++)
#pragma unroll
        for (int nf = 0; nf < 4; nf++)
#pragma unroll
            for (int r = 0; r < 4; r++) acc[mf][nf][r] = 0.f;

    for (int c = 0; c < 4; c++) {
        __syncthreads();
#pragma unroll
        for (int p = 0; p < 8; p++) {
            const int row = p * 32 + (t >> 3), c4 = (t & 7) * 4;
            float4 v = *(const float4*)(Vb + (size_t)(c * 256 + row) * HIDC + c4);
            float vv[4] = {v.x, v.y, v.z, v.w};
#pragma unroll
            for (int j = 0; j < 4; j++) {
                uint32_t hi = f2tf32(vv[j]);
                kh[row * KST + c4 + j] = hi;
                kl[row * KST + c4 + j] = f2tf32(vv[j] - __uint_as_float(hi));
            }
        }
        __syncthreads();

        const int kw = wid * 32;
#pragma unroll
        for (int ks = 0; ks < 4; ks++) {
            const int kLoc  = kw + ks * 8 + t4;
            const int kGlob = c * 256 + kLoc;
            uint32_t ah[2][4], al[2][4];
#pragma unroll
            for (int mf = 0; mf < 2; mf++) {
                const int d0 = mf * 16 + g;
                const int a0 = kLoc * KST + d0;
                const int a4 = (kLoc + 4) * KST + d0;
                ah[mf][0] = kh[a0];
                ah[mf][1] = kh[a0 + 8];
                ah[mf][2] = kh[a4];
                ah[mf][3] = kh[a4 + 8];
                al[mf][0] = kl[a0];
                al[mf][1] = kl[a0 + 8];
                al[mf][2] = kl[a4];
                al[mf][3] = kl[a4 + 8];
            }
#pragma unroll
            for (int nf = 0; nf < 4; nf++) {
                const int q = nf * 8 + g;
                const float p0 = S[q * SST + kGlob];
                const float p1 = S[q * SST + kGlob + 4];
                uint32_t bh2[2], bl2[2];
                bh2[0] = f2tf32(p0); bl2[0] = f2tf32(p0 - __uint_as_float(bh2[0]));
                bh2[1] = f2tf32(p1); bl2[1] = f2tf32(p1 - __uint_as_float(bh2[1]));
#pragma unroll
                for (int mf = 0; mf < 2; mf++) {
                    mma_tf32(acc[mf][nf], ah[mf], bh2);
                    mma_tf32(acc[mf][nf], ah[mf], bl2);
                    mma_tf32(acc[mf][nf], al[mf], bh2);
                }
            }
        }
    }
    __syncthreads();

    float* red = sm + OFF_KH;
#pragma unroll
    for (int mf = 0; mf < 2; mf++)
#pragma unroll
        for (int nf = 0; nf < 4; nf++) {
            const int d = mf * 16 + g;
            const int q = nf * 8 + 2 * t4;
            float* rw = red + wid * 1056;
            rw[q * 33 + d]           = acc[mf][nf][0];
            rw[(q + 1) * 33 + d]     = acc[mf][nf][1];
            rw[q * 33 + d + 8]       = acc[mf][nf][2];
            rw[(q + 1) * 33 + d + 8] = acc[mf][nf][3];
        }
    __syncthreads();

#pragma unroll
    for (int i = 0; i < 4; i++) {
        const int idx = t + i * 256;
        const int q = idx >> 5, d = idx & 31;
        float s = 0.f;
#pragma unroll
        for (int w = 0; w < 8; w++) s += red[w * 1056 + q * 33 + d];
        g_ctx[(size_t)(b * SEQ + q0 + q) * HIDC + h * HDC + d] = s;
    }
}

// ---------------------------------------------------------------------------
// LayerNorm (unchanged)
// ---------------------------------------------------------------------------
__global__ void ln_kernel(const float* __restrict__ gamma,
                          const float* __restrict__ beta,
                          float* __restrict__ out)
{
    __shared__ float red[8];
    const int row = blockIdx.x, t = threadIdx.x;
    const int w = t >> 5, lane = t & 31;

    float4 v = *((const float4*)(g_x + (size_t)row * HIDC) + t);
    float s = v.x + v.y + v.z + v.w;
#pragma unroll
    for (int o = 16; o > 0; o >>= 1) s += __shfl_xor_sync(0xffffffffu, s, o);
    if (lane == 0) red[w] = s;
    __syncthreads();
    if (t == 0) {
        float tt = 0.f;
#pragma unroll
        for (int i = 0; i < 8; i++) tt += red[i];
        red[0] = tt;
    }
    __syncthreads();
    const float mu = red[0] * (1.f / 1024.f);
    __syncthreads();

    float dx = v.x - mu, dy = v.y - mu, dz = v.z - mu, dw = v.w - mu;
    float sq = dx * dx + dy * dy + dz * dz + dw * dw;
#pragma unroll
    for (int o = 16; o > 0; o >>= 1) sq += __shfl_xor_sync(0xffffffffu, sq, o);
    if (lane == 0) red[w] = sq;
    __syncthreads();
    if (t == 0) {
        float tt = 0.f;
#pragma unroll
        for (int i = 0; i < 8; i++) tt += red[i];
        red[0] = tt;
    }
    __syncthreads();
    const float inv = rsqrtf(red[0] * (1.f / 1024.f) + 1e-12f);

    float4 g  = *((const float4*)gamma + t);
    float4 bt = *((const float4*)beta + t);
    float4 o4;
    o4.x = dx * inv * g.x + bt.x;
    o4.y = dy * inv * g.y + bt.y;
    o4.z = dz * inv * g.z + bt.z;
    o4.w = dw * inv * g.w + bt.w;
    *((float4*)(out + (size_t)row * HIDC) + t) = o4;
}

// ---------------------------------------------------------------------------
// Launch
// ---------------------------------------------------------------------------
extern "C" void kernel_launch(void* const* d_in, const int* in_sizes, int n_in,
                              void* d_out, int out_size)
{
    (void)in_sizes; (void)n_in; (void)out_size;
    const float* hidden = (const float*)d_in[0];
    const float* Wq = (const float*)d_in[1];
    const float* bq = (const float*)d_in[2];
    const float* Wk = (const float*)d_in[3];
    const float* bk = (const float*)d_in[4];
    const float* Wv = (const float*)d_in[5];
    const float* bv = (const float*)d_in[6];
    const float* Wo = (const float*)d_in[7];
    const float* bo = (const float*)d_in[8];
    const float* gamma = (const float*)d_in[9];
    const float* beta  = (const float*)d_in[10];
    const float* dist  = (const float*)d_in[11];

    float* out   = (float*)d_out;
    float* probs = out + (size_t)BATCH * SEQ * HIDC;

    cudaFuncSetAttribute(attn_kernel, cudaFuncAttributeMaxDynamicSharedMemorySize,
                         (int)ATTN_SMEM_BYTES);

    // Prepass conversions — destinations resolved in device code via `which`
    constexpr int HW = MR * WR;          // hidden words: 2M
    constexpr int WW = HIDC * WR;        // per-W words: 512K
    cvt_kernel<<<HW / 512, 256>>>(hidden, 0, HW);
    cvt_kernel<<<WW / 512, 256>>>(Wq, 1, WW);
    cvt_kernel<<<WW / 512, 256>>>(Wk, 2, WW);
    cvt_kernel<<<WW / 512, 256>>>(Wv, 3, WW);

    qkv_gemm<<<dim3(8, 32, 3), 256>>>(bq, bk, bv);
    attn_kernel<<<dim3(32, 32, 4), 256, ATTN_SMEM_BYTES>>>(dist, probs);
    o_gemm<<<dim3(8, 32, 1), 256>>>(Wo, bo, hidden);
    ln_kernel<<<MR, 256>>>(gamma, beta, out);
}

// round 14
// speedup vs baseline: 1.2061x; 1.2061x over previous
#include <cuda_runtime.h>
#include <cuda_bf16.h>
#include <cstdint>
#include <cstddef>

// Problem constants
constexpr int SEQ   = 1024;
constexpr int HIDC  = 1024;
constexpr int NHC   = 32;
constexpr int HDC   = 32;
constexpr int BATCH = 4;
constexpr int MR    = BATCH * SEQ;   // 4096 rows

// Scratch
__device__ float g_q[(size_t)MR * HIDC];
__device__ float g_k[(size_t)MR * HIDC];
__device__ float g_v[(size_t)MR * HIDC];
__device__ float g_ctx[(size_t)MR * HIDC];
__device__ float g_x[(size_t)MR * HIDC];

__device__ __forceinline__ void mma_bf16(float* c, const uint32_t* a, const uint32_t* b) {
    asm volatile(
        "mma.sync.aligned.m16n8k16.row.col.f32.bf16.bf16.f32 "
        "{%0,%1,%2,%3}, {%4,%5,%6,%7}, {%8,%9}, {%0,%1,%2,%3};\n"
        : "+f"(c[0]), "+f"(c[1]), "+f"(c[2]), "+f"(c[3])
        : "r"(a[0]), "r"(a[1]), "r"(a[2]), "r"(a[3]), "r"(b[0]), "r"(b[1]));
}

// Split f32 pair -> bf16x2 hi word + bf16x2 residual word.
__device__ __forceinline__ void cvt_pair(float x, float y, uint32_t& hi, uint32_t& lo) {
    __nv_bfloat162 h = __float22bfloat162_rn(make_float2(x, y));
    float2 hf = __bfloat1622float2(h);
    __nv_bfloat162 l = __float22bfloat162_rn(make_float2(x - hf.x, y - hf.y));
    hi = *reinterpret_cast<uint32_t*>(&h);
    lo = *reinterpret_cast<uint32_t*>(&l);
}

// ---------------------------------------------------------------------------
// 3xBF16 tensor-core GEMM (R8-verbatim): C = A @ B^T + bias (+resid)
// CTA tile 128x128x16, 8 warps (2M x 4N), 2-stage smem ping-pong.
// ---------------------------------------------------------------------------
constexpr int LDB = 12;

__device__ __forceinline__ void gemm_tc_body(const float* __restrict__ A,
                                             const float* __restrict__ B,
                                             const float* __restrict__ bias,
                                             const float* __restrict__ resid,
                                             float* __restrict__ C)
{
    __shared__ uint32_t sAh[2][128 * LDB], sAl[2][128 * LDB];
    __shared__ uint32_t sBh[2][128 * LDB], sBl[2][128 * LDB];

    const int t    = threadIdx.x;
    const int m0   = blockIdx.y * 128;
    const int n0   = blockIdx.x * 128;
    const int wid  = t >> 5, lane = t & 31;
    const int wm   = wid & 1, wn = wid >> 1;
    const int g    = lane >> 2, t4 = lane & 3;

    const int lr = t >> 2;             // 0..63
    const int lw = (t & 3) * 2;        // word offset 0,2,4,6
    const float* Ap = A + (size_t)(m0 + lr) * HIDC + (t & 3) * 4;
    const float* Bp = B + (size_t)(n0 + lr) * HIDC + (t & 3) * 4;

    float acc[4][4][4];
#pragma unroll
    for (int i = 0; i < 4; i++)
#pragma unroll
        for (int j = 0; j < 4; j++)
#pragma unroll
            for (int r = 0; r < 4; r++) acc[i][j][r] = 0.f;

    float4 ra0, ra1, rb0, rb1;
    auto gload = [&](int kt) {
        const float* a = Ap + kt * 16;
        const float* b = Bp + kt * 16;
        ra0 = *(const float4*)(a);
        ra1 = *(const float4*)(a + (size_t)64 * HIDC);
        rb0 = *(const float4*)(b);
        rb1 = *(const float4*)(b + (size_t)64 * HIDC);
    };
    auto sts = [&](int st) {
        uint32_t h0, l0, h1, l1;
        cvt_pair(ra0.x, ra0.y, h0, l0); cvt_pair(ra0.z, ra0.w, h1, l1);
        sAh[st][lr * LDB + lw] = h0; sAh[st][lr * LDB + lw + 1] = h1;
        sAl[st][lr * LDB + lw] = l0; sAl[st][lr * LDB + lw + 1] = l1;
        cvt_pair(ra1.x, ra1.y, h0, l0); cvt_pair(ra1.z, ra1.w, h1, l1);
        sAh[st][(lr + 64) * LDB + lw] = h0; sAh[st][(lr + 64) * LDB + lw + 1] = h1;
        sAl[st][(lr + 64) * LDB + lw] = l0; sAl[st][(lr + 64) * LDB + lw + 1] = l1;
        cvt_pair(rb0.x, rb0.y, h0, l0); cvt_pair(rb0.z, rb0.w, h1, l1);
        sBh[st][lr * LDB + lw] = h0; sBh[st][lr * LDB + lw + 1] = h1;
        sBl[st][lr * LDB + lw] = l0; sBl[st][lr * LDB + lw + 1] = l1;
        cvt_pair(rb1.x, rb1.y, h0, l0); cvt_pair(rb1.z, rb1.w, h1, l1);
        sBh[st][(lr + 64) * LDB + lw] = h0; sBh[st][(lr + 64) * LDB + lw + 1] = h1;
        sBl[st][(lr + 64) * LDB + lw] = l0; sBl[st][(lr + 64) * LDB + lw + 1] = l1;
    };

    gload(0);
    sts(0);
    __syncthreads();

    for (int kt = 0; kt < HIDC / 16; kt++) {
        const int st = kt & 1;
        if (kt + 1 < HIDC / 16) gload(kt + 1);

        uint32_t bh[4][2], bl[4][2];
#pragma unroll
        for (int nf = 0; nf < 4; nf++) {
            const int n = (wn * 32 + nf * 8 + g) * LDB;
            bh[nf][0] = sBh[st][n + t4];
            bh[nf][1] = sBh[st][n + t4 + 4];
            bl[nf][0] = sBl[st][n + t4];
            bl[nf][1] = sBl[st][n + t4 + 4];
        }
#pragma unroll
        for (int mf = 0; mf < 4; mf++) {
            const int m = (wm * 64 + mf * 16 + g) * LDB;
            uint32_t ah[4], al[4];
            ah[0] = sAh[st][m + t4];
            ah[1] = sAh[st][m + 8 * LDB + t4];
            ah[2] = sAh[st][m + t4 + 4];
            ah[3] = sAh[st][m + 8 * LDB + t4 + 4];
            al[0] = sAl[st][m + t4];
            al[1] = sAl[st][m + 8 * LDB + t4];
            al[2] = sAl[st][m + t4 + 4];
            al[3] = sAl[st][m + 8 * LDB + t4 + 4];
#pragma unroll
            for (int nf = 0; nf < 4; nf++) {
                mma_bf16(acc[mf][nf], ah, bh[nf]);
                mma_bf16(acc[mf][nf], ah, bl[nf]);
                mma_bf16(acc[mf][nf], al, bh[nf]);
            }
        }

        if (kt + 1 < HIDC / 16) {
            sts((kt + 1) & 1);
            __syncthreads();
        }
    }

#pragma unroll
    for (int mf = 0; mf < 4; mf++) {
#pragma unroll
        for (int nf = 0; nf < 4; nf++) {
            const int row = m0 + wm * 64 + mf * 16 + g;
            const int col = n0 + wn * 32 + nf * 8 + t4 * 2;
            float2 bb = *(const float2*)(bias + col);
            float2 o0, o1;
            o0.x = acc[mf][nf][0] + bb.x;
            o0.y = acc[mf][nf][1] + bb.y;
            o1.x = acc[mf][nf][2] + bb.x;
            o1.y = acc[mf][nf][3] + bb.y;
            if (resid != nullptr) {
                float2 r0 = *(const float2*)(resid + (size_t)row * HIDC + col);
                float2 r1 = *(const float2*)(resid + (size_t)(row + 8) * HIDC + col);
                o0.x += r0.x; o0.y += r0.y;
                o1.x += r1.x; o1.y += r1.y;
            }
            *(float2*)(C + (size_t)row * HIDC + col)       = o0;
            *(float2*)(C + (size_t)(row + 8) * HIDC + col) = o1;
        }
    }
}

__global__ __launch_bounds__(256, 2) void qkv_gemm(const float* __restrict__ H,
    const float* __restrict__ Wq, const float* __restrict__ bq,
    const float* __restrict__ Wk, const float* __restrict__ bk,
    const float* __restrict__ Wv, const float* __restrict__ bv)
{
    const float* W;
    const float* bias;
    float* out;
    if (blockIdx.z == 0)      { W = Wq; bias = bq; out = g_q; }
    else if (blockIdx.z == 1) { W = Wk; bias = bk; out = g_k; }
    else                      { W = Wv; bias = bv; out = g_v; }
    gemm_tc_body(H, W, bias, nullptr, out);
}

__global__ __launch_bounds__(256, 2) void o_gemm(const float* __restrict__ Wo,
    const float* __restrict__ bo, const float* __restrict__ H)
{
    gemm_tc_body(g_ctx, Wo, bo, H, g_x);
}

// ---------------------------------------------------------------------------
// Tensor-core fused attention. Per block: (b, h, 32 q-rows). All 3xBF16.
//  Phase 1: S = (Q K^T + bias)/sqrt(32) via 3xBF16 m16n8k16 (R8-verbatim)
//  Phase 2: exact softmax; write probs; normalized P back to S (R8-verbatim)
//  Phase 3: ctx^T = V^T P^T via 3xBF16 m16n8k16 (V fp32 in smem, key-pairs
//           built on the fly) — replaces R8's 3xTF32, halving phase-3 MMAs.
// ---------------------------------------------------------------------------
constexpr int SST  = 1032;  // S row stride (floats)
constexpr int KSTB = 20;    // phase-1 bf16 row stride (words; 16 used)

constexpr int OFF_S  = 0;
constexpr int OFF_KH = 33024;               // phase1 kh / phase3 V fp32 (256*36=9216) / red (8448)
constexpr int OFF_KL = OFF_KH + 8448;
constexpr int OFF_QH = OFF_KL + 8448;
constexpr int OFF_QL = OFF_QH + 1056;
constexpr int OFF_BS = OFF_QL + 1056;
constexpr int ATTN_FLOATS = OFF_BS + 1056;  // 53088
constexpr size_t ATTN_SMEM_BYTES = (size_t)ATTN_FLOATS * sizeof(float);

__global__ __launch_bounds__(256, 1) void attn_kernel(const float* __restrict__ dist_emb,
                                                      float* __restrict__ probs_out)
{
    extern __shared__ float sm[];
    float*    S  = sm + OFF_S;
    uint32_t* kh = (uint32_t*)(sm + OFF_KH);
    uint32_t* kl = (uint32_t*)(sm + OFF_KL);
    uint32_t* qh = (uint32_t*)(sm + OFF_QH);
    uint32_t* ql = (uint32_t*)(sm + OFF_QL);
    float*    bs = sm + OFF_BS;

    const int t   = threadIdx.x;
    const int q0  = blockIdx.x * 32;
    const int h   = blockIdx.y;
    const int b   = blockIdx.z;
    const int wid = t >> 5, lane = t & 31;
    const int g   = lane >> 2, t4 = lane & 3;

    const size_t bh_off = (size_t)b * SEQ * HIDC + (size_t)h * HDC;
    const float* Qb = g_q + bh_off;
    const float* Kb = g_k + bh_off;
    const float* Vb = g_v + bh_off;

    for (int r = t; r < 1055; r += 256)
        bs[r] = dist_emb[(size_t)(q0 + r) * HDC + h];

    // stage Q tile (32x32) as bf16 hi/lo pair-words
    {
        const int row = t >> 3, c4 = (t & 7) * 4, w2 = (t & 7) * 2;
        float4 v = *(const float4*)(Qb + (size_t)(q0 + row) * HIDC + c4);
        uint32_t h0, l0, h1, l1;
        cvt_pair(v.x, v.y, h0, l0);
        cvt_pair(v.z, v.w, h1, l1);
        qh[row * KSTB + w2]     = h0;
        qh[row * KSTB + w2 + 1] = h1;
        ql[row * KSTB + w2]     = l0;
        ql[row * KSTB + w2 + 1] = l1;
    }
    __syncthreads();

    uint32_t qfh[2][2][4], qfl[2][2][4];
#pragma unroll
    for (int mf = 0; mf < 2; mf++)
#pragma unroll
        for (int ks = 0; ks < 2; ks++) {
            const int r0 = (mf * 16 + g) * KSTB;
            const int r1 = r0 + 8 * KSTB;
            const int k0 = ks * 8 + t4;
            qfh[mf][ks][0] = qh[r0 + k0];
            qfh[mf][ks][1] = qh[r1 + k0];
            qfh[mf][ks][2] = qh[r0 + k0 + 4];
            qfh[mf][ks][3] = qh[r1 + k0 + 4];
            qfl[mf][ks][0] = ql[r0 + k0];
            qfl[mf][ks][1] = ql[r1 + k0];
            qfl[mf][ks][2] = ql[r0 + k0 + 4];
            qfl[mf][ks][3] = ql[r1 + k0 + 4];
        }

    const float scale = 0.17677669529663688f;

    // ---- Phase 1 ----
    for (int c = 0; c < 4; c++) {
        __syncthreads();
#pragma unroll
        for (int p = 0; p < 8; p++) {
            const int row = p * 32 + (t >> 3), c4 = (t & 7) * 4, w2 = (t & 7) * 2;
            float4 v = *(const float4*)(Kb + (size_t)(c * 256 + row) * HIDC + c4);
            uint32_t h0, l0, h1, l1;
            cvt_pair(v.x, v.y, h0, l0);
            cvt_pair(v.z, v.w, h1, l1);
            kh[row * KSTB + w2]     = h0;
            kh[row * KSTB + w2 + 1] = h1;
            kl[row * KSTB + w2]     = l0;
            kl[row * KSTB + w2 + 1] = l1;
        }
        __syncthreads();

        const int kw = wid * 32;
#pragma unroll
        for (int nf = 0; nf < 4; nf++) {
            uint32_t bhh[2][2], bll[2][2];
#pragma unroll
            for (int ks = 0; ks < 2; ks++) {
                const int n = (kw + nf * 8 + g) * KSTB + ks * 8 + t4;
                bhh[ks][0] = kh[n]; bhh[ks][1] = kh[n + 4];
                bll[ks][0] = kl[n]; bll[ks][1] = kl[n + 4];
            }
#pragma unroll
            for (int mf = 0; mf < 2; mf++) {
                float acc[4] = {0.f, 0.f, 0.f, 0.f};
#pragma unroll
                for (int ks = 0; ks < 2; ks++) {
                    mma_bf16(acc, qfh[mf][ks], bhh[ks]);
                    mma_bf16(acc, qfh[mf][ks], bll[ks]);
                    mma_bf16(acc, qfl[mf][ks], bhh[ks]);
                }
                const int row0 = mf * 16 + g;
                const int row1 = row0 + 8;
                const int col  = c * 256 + kw + nf * 8 + 2 * t4;
                float2 s0, s1;
                s0.x = (acc[0] + bs[row0 - col + 1023]) * scale;
                s0.y = (acc[1] + bs[row0 - col + 1022]) * scale;
                s1.x = (acc[2] + bs[row1 - col + 1023]) * scale;
                s1.y = (acc[3] + bs[row1 - col + 1022]) * scale;
                *(float2*)&S[row0 * SST + col] = s0;
                *(float2*)&S[row1 * SST + col] = s1;
            }
        }
    }
    __syncthreads();

    // ---- Phase 2 ----
    {
        float* pb = probs_out + ((size_t)(b * NHC + h) * SEQ + q0) * SEQ;
        for (int rr = 0; rr < 4; rr++) {
            const int r = wid + 8 * rr;
            float* row = S + r * SST;
            float mx = -1e30f;
            for (int i = lane; i < 1024; i += 32) mx = fmaxf(mx, row[i]);
#pragma unroll
            for (int o = 16; o > 0; o >>= 1)
                mx = fmaxf(mx, __shfl_xor_sync(0xffffffffu, mx, o));
            float sum = 0.f;
            for (int i = lane; i < 1024; i += 32) {
                float e = __expf(row[i] - mx);
                row[i] = e;
                sum += e;
            }
#pragma unroll
            for (int o = 16; o > 0; o >>= 1)
                sum += __shfl_xor_sync(0xffffffffu, sum, o);
            const float inv = 1.f / sum;
            float* pr = pb + (size_t)r * SEQ;
            for (int i = lane; i < 1024; i += 32) {
                float p = row[i] * inv;
                row[i] = p;
                pr[i]  = p;
            }
        }
    }

    // ---- Phase 3: ctx^T = V^T @ P^T via 3xBF16 m16n8k16 (m=dim, n=q, k=key)
    float* kvf = sm + OFF_KH;  // 256 x 36 fp32 V chunk (reuses kh/kl region)

    float acc[2][4][4];
#pragma unroll
    for (int mf = 0; mf < 2; mf++)
#pragma unroll
        for (int nf = 0; nf < 4; nf++)
#pragma unroll
            for (int r = 0; r < 4; r++) acc[mf][nf][r] = 0.f;

    for (int c = 0; c < 4; c++) {
        __syncthreads();
#pragma unroll
        for (int p = 0; p < 8; p++) {
            const int row = p * 32 + (t >> 3), c4 = (t & 7) * 4;
            *(float4*)&kvf[row * 36 + c4] =
                *(const float4*)(Vb + (size_t)(c * 256 + row) * HIDC + c4);
        }
        __syncthreads();

        const int kw = wid * 32;
#pragma unroll
        for (int ks = 0; ks < 2; ks++) {
            const int base = kw + ks * 16;
            const int k0   = base + 2 * t4;   // even key (this lane's k-pair)
            // A fragments: A[m=d][k=key] = V[key][d]; words pair adjacent keys
            uint32_t ah[2][4], al[2][4];
#pragma unroll
            for (int mf = 0; mf < 2; mf++) {
                const int d = mf * 16 + g;
                cvt_pair(kvf[k0 * 36 + d],           kvf[(k0 + 1) * 36 + d],
                         ah[mf][0], al[mf][0]);
                cvt_pair(kvf[k0 * 36 + d + 8],       kvf[(k0 + 1) * 36 + d + 8],
                         ah[mf][1], al[mf][1]);
                cvt_pair(kvf[(k0 + 8) * 36 + d],     kvf[(k0 + 9) * 36 + d],
                         ah[mf][2], al[mf][2]);
                cvt_pair(kvf[(k0 + 8) * 36 + d + 8], kvf[(k0 + 9) * 36 + d + 8],
                         ah[mf][3], al[mf][3]);
            }
            const int gbase = c * 256 + base;
#pragma unroll
            for (int nf = 0; nf < 4; nf++) {
                const int q = nf * 8 + g;
                float2 p0 = *(const float2*)&S[q * SST + gbase + 2 * t4];
                float2 p1 = *(const float2*)&S[q * SST + gbase + 8 + 2 * t4];
                uint32_t bh2[2], bl2[2];
                cvt_pair(p0.x, p0.y, bh2[0], bl2[0]);
                cvt_pair(p1.x, p1.y, bh2[1], bl2[1]);
#pragma unroll
                for (int mf = 0; mf < 2; mf++) {
                    mma_bf16(acc[mf][nf], ah[mf], bh2);
                    mma_bf16(acc[mf][nf], ah[mf], bl2);
                    mma_bf16(acc[mf][nf], al[mf], bh2);
                }
            }
        }
    }
    __syncthreads();

    // cross-warp reduction of partial ctx (same accumulator layout as R8:
    // c0=(d, q), c1=(d, q+1), c2=(d+8, q), c3=(d+8, q+1) with q = nf*8+2*t4)
    float* red = sm + OFF_KH;
#pragma unroll
    for (int mf = 0; mf < 2; mf++)
#pragma unroll
        for (int nf = 0; nf < 4; nf++) {
            const int d = mf * 16 + g;
            const int q = nf * 8 + 2 * t4;
            float* rw = red + wid * 1056;
            rw[q * 33 + d]           = acc[mf][nf][0];
            rw[(q + 1) * 33 + d]     = acc[mf][nf][1];
            rw[q * 33 + d + 8]       = acc[mf][nf][2];
            rw[(q + 1) * 33 + d + 8] = acc[mf][nf][3];
        }
    __syncthreads();

#pragma unroll
    for (int i = 0; i < 4; i++) {
        const int idx = t + i * 256;
        const int q = idx >> 5, d = idx & 31;
        float s = 0.f;
#pragma unroll
        for (int w = 0; w < 8; w++) s += red[w * 1056 + q * 33 + d];
        g_ctx[(size_t)(b * SEQ + q0 + q) * HIDC + h * HDC + d] = s;
    }
}

// ---------------------------------------------------------------------------
// LayerNorm (unchanged)
// ---------------------------------------------------------------------------
__global__ void ln_kernel(const float* __restrict__ gamma,
                          const float* __restrict__ beta,
                          float* __restrict__ out)
{
    __shared__ float red[8];
    const int row = blockIdx.x, t = threadIdx.x;
    const int w = t >> 5, lane = t & 31;

    float4 v = *((const float4*)(g_x + (size_t)row * HIDC) + t);
    float s = v.x + v.y + v.z + v.w;
#pragma unroll
    for (int o = 16; o > 0; o >>= 1) s += __shfl_xor_sync(0xffffffffu, s, o);
    if (lane == 0) red[w] = s;
    __syncthreads();
    if (t == 0) {
        float tt = 0.f;
#pragma unroll
        for (int i = 0; i < 8; i++) tt += red[i];
        red[0] = tt;
    }
    __syncthreads();
    const float mu = red[0] * (1.f / 1024.f);
    __syncthreads();

    float dx = v.x - mu, dy = v.y - mu, dz = v.z - mu, dw = v.w - mu;
    float sq = dx * dx + dy * dy + dz * dz + dw * dw;
#pragma unroll
    for (int o = 16; o > 0; o >>= 1) sq += __shfl_xor_sync(0xffffffffu, sq, o);
    if (lane == 0) red[w] = sq;
    __syncthreads();
    if (t == 0) {
        float tt = 0.f;
#pragma unroll
        for (int i = 0; i < 8; i++) tt += red[i];
        red[0] = tt;
    }
    __syncthreads();
    const float inv = rsqrtf(red[0] * (1.f / 1024.f) + 1e-12f);

    float4 g  = *((const float4*)gamma + t);
    float4 bt = *((const float4*)beta + t);
    float4 o4;
    o4.x = dx * inv * g.x + bt.x;
    o4.y = dy * inv * g.y + bt.y;
    o4.z = dz * inv * g.z + bt.z;
    o4.w = dw * inv * g.w + bt.w;
    *((float4*)(out + (size_t)row * HIDC) + t) = o4;
}

// ---------------------------------------------------------------------------
// Launch
// ---------------------------------------------------------------------------
extern "C" void kernel_launch(void* const* d_in, const int* in_sizes, int n_in,
                              void* d_out, int out_size)
{
    (void)in_sizes; (void)n_in; (void)out_size;
    const float* hidden = (const float*)d_in[0];
    const float* Wq = (const float*)d_in[1];
    const float* bq = (const float*)d_in[2];
    const float* Wk = (const float*)d_in[3];
    const float* bk = (const float*)d_in[4];
    const float* Wv = (const float*)d_in[5];
    const float* bv = (const float*)d_in[6];
    const float* Wo = (const float*)d_in[7];
    const float* bo = (const float*)d_in[8];
    const float* gamma = (const float*)d_in[9];
    const float* beta  = (const float*)d_in[10];
    const float* dist  = (const float*)d_in[11];

    float* out   = (float*)d_out;
    float* probs = out + (size_t)BATCH * SEQ * HIDC;

    cudaFuncSetAttribute(attn_kernel, cudaFuncAttributeMaxDynamicSharedMemorySize,
                         (int)ATTN_SMEM_BYTES);

    qkv_gemm<<<dim3(8, 32, 3), 256>>>(hidden, Wq, bq, Wk, bk, Wv, bv);
    attn_kernel<<<dim3(32, 32, 4), 256, ATTN_SMEM_BYTES>>>(dist, probs);
    o_gemm<<<dim3(8, 32, 1), 256>>>(Wo, bo, hidden);
    ln_kernel<<<MR, 256>>>(gamma, beta, out);
}

// round 15
// speedup vs baseline: 1.3631x; 1.1301x over previous
#include <cuda_runtime.h>
#include <cuda_fp16.h>
#include <cstdint>
#include <cstddef>

// Problem constants
constexpr int SEQ   = 1024;
constexpr int HIDC  = 1024;
constexpr int NHC   = 32;
constexpr int HDC   = 32;
constexpr int BATCH = 4;
constexpr int MR    = BATCH * SEQ;   // 4096 rows

// Scratch
__device__ float g_q[(size_t)MR * HIDC];
__device__ float g_k[(size_t)MR * HIDC];
__device__ float g_v[(size_t)MR * HIDC];
__device__ float g_ctx[(size_t)MR * HIDC];
__device__ float g_x[(size_t)MR * HIDC];

__device__ __forceinline__ void mma_f16(float* c, const uint32_t* a, const uint32_t* b) {
    asm volatile(
        "mma.sync.aligned.m16n8k16.row.col.f32.f16.f16.f32 "
        "{%0,%1,%2,%3}, {%4,%5,%6,%7}, {%8,%9}, {%0,%1,%2,%3};\n"
        : "+f"(c[0]), "+f"(c[1]), "+f"(c[2]), "+f"(c[3])
        : "r"(a[0]), "r"(a[1]), "r"(a[2]), "r"(a[3]), "r"(b[0]), "r"(b[1]));
}

// Split f32 pair -> fp16x2 hi word + fp16x2 residual word.
__device__ __forceinline__ void cvt_pair_h(float x, float y, uint32_t& hi, uint32_t& lo) {
    __half2 h = __floats2half2_rn(x, y);
    float2 hf = __half22float2(h);
    __half2 l = __floats2half2_rn(x - hf.x, y - hf.y);
    hi = *reinterpret_cast<uint32_t*>(&h);
    lo = *reinterpret_cast<uint32_t*>(&l);
}

// f32 pair -> single fp16x2 word.
__device__ __forceinline__ uint32_t cvt_h2(float x, float y) {
    __half2 h = __floats2half2_rn(x, y);
    return *reinterpret_cast<uint32_t*>(&h);
}

// ---------------------------------------------------------------------------
// 2xFP16 tensor-core GEMM: C = A @ B^T + bias (+resid)
// A (large sigma) split hi/lo fp16; B (weights) single fp16.
// CTA tile 128x128x16, 8 warps (2M x 4N), 2-stage smem ping-pong.
// ---------------------------------------------------------------------------
constexpr int LDB = 12;

__device__ __forceinline__ void gemm_tc_body(const float* __restrict__ A,
                                             const float* __restrict__ B,
                                             const float* __restrict__ bias,
                                             const float* __restrict__ resid,
                                             float* __restrict__ C)
{
    __shared__ uint32_t sAh[2][128 * LDB], sAl[2][128 * LDB];
    __shared__ uint32_t sB[2][128 * LDB];

    const int t    = threadIdx.x;
    const int m0   = blockIdx.y * 128;
    const int n0   = blockIdx.x * 128;
    const int wid  = t >> 5, lane = t & 31;
    const int wm   = wid & 1, wn = wid >> 1;
    const int g    = lane >> 2, t4 = lane & 3;

    const int lr = t >> 2;             // 0..63
    const int lw = (t & 3) * 2;        // word offset 0,2,4,6
    const float* Ap = A + (size_t)(m0 + lr) * HIDC + (t & 3) * 4;
    const float* Bp = B + (size_t)(n0 + lr) * HIDC + (t & 3) * 4;

    float acc[4][4][4];
#pragma unroll
    for (int i = 0; i < 4; i++)
#pragma unroll
        for (int j = 0; j < 4; j++)
#pragma unroll
            for (int r = 0; r < 4; r++) acc[i][j][r] = 0.f;

    float4 ra0, ra1, rb0, rb1;
    auto gload = [&](int kt) {
        const float* a = Ap + kt * 16;
        const float* b = Bp + kt * 16;
        ra0 = *(const float4*)(a);
        ra1 = *(const float4*)(a + (size_t)64 * HIDC);
        rb0 = *(const float4*)(b);
        rb1 = *(const float4*)(b + (size_t)64 * HIDC);
    };
    auto sts = [&](int st) {
        uint32_t h0, l0, h1, l1;
        cvt_pair_h(ra0.x, ra0.y, h0, l0); cvt_pair_h(ra0.z, ra0.w, h1, l1);
        sAh[st][lr * LDB + lw] = h0; sAh[st][lr * LDB + lw + 1] = h1;
        sAl[st][lr * LDB + lw] = l0; sAl[st][lr * LDB + lw + 1] = l1;
        cvt_pair_h(ra1.x, ra1.y, h0, l0); cvt_pair_h(ra1.z, ra1.w, h1, l1);
        sAh[st][(lr + 64) * LDB + lw] = h0; sAh[st][(lr + 64) * LDB + lw + 1] = h1;
        sAl[st][(lr + 64) * LDB + lw] = l0; sAl[st][(lr + 64) * LDB + lw + 1] = l1;
        sB[st][lr * LDB + lw]            = cvt_h2(rb0.x, rb0.y);
        sB[st][lr * LDB + lw + 1]        = cvt_h2(rb0.z, rb0.w);
        sB[st][(lr + 64) * LDB + lw]     = cvt_h2(rb1.x, rb1.y);
        sB[st][(lr + 64) * LDB + lw + 1] = cvt_h2(rb1.z, rb1.w);
    };

    gload(0);
    sts(0);
    __syncthreads();

    for (int kt = 0; kt < HIDC / 16; kt++) {
        const int st = kt & 1;
        if (kt + 1 < HIDC / 16) gload(kt + 1);

        uint32_t bfr[4][2];
#pragma unroll
        for (int nf = 0; nf < 4; nf++) {
            const int n = (wn * 32 + nf * 8 + g) * LDB;
            bfr[nf][0] = sB[st][n + t4];
            bfr[nf][1] = sB[st][n + t4 + 4];
        }
#pragma unroll
        for (int mf = 0; mf < 4; mf++) {
            const int m = (wm * 64 + mf * 16 + g) * LDB;
            uint32_t ah[4], al[4];
            ah[0] = sAh[st][m + t4];
            ah[1] = sAh[st][m + 8 * LDB + t4];
            ah[2] = sAh[st][m + t4 + 4];
            ah[3] = sAh[st][m + 8 * LDB + t4 + 4];
            al[0] = sAl[st][m + t4];
            al[1] = sAl[st][m + 8 * LDB + t4];
            al[2] = sAl[st][m + t4 + 4];
            al[3] = sAl[st][m + 8 * LDB + t4 + 4];
#pragma unroll
            for (int nf = 0; nf < 4; nf++) {
                mma_f16(acc[mf][nf], ah, bfr[nf]);
                mma_f16(acc[mf][nf], al, bfr[nf]);
            }
        }

        if (kt + 1 < HIDC / 16) {
            sts((kt + 1) & 1);
            __syncthreads();
        }
    }

#pragma unroll
    for (int mf = 0; mf < 4; mf++) {
#pragma unroll
        for (int nf = 0; nf < 4; nf++) {
            const int row = m0 + wm * 64 + mf * 16 + g;
            const int col = n0 + wn * 32 + nf * 8 + t4 * 2;
            float2 bb = *(const float2*)(bias + col);
            float2 o0, o1;
            o0.x = acc[mf][nf][0] + bb.x;
            o0.y = acc[mf][nf][1] + bb.y;
            o1.x = acc[mf][nf][2] + bb.x;
            o1.y = acc[mf][nf][3] + bb.y;
            if (resid != nullptr) {
                float2 r0 = *(const float2*)(resid + (size_t)row * HIDC + col);
                float2 r1 = *(const float2*)(resid + (size_t)(row + 8) * HIDC + col);
                o0.x += r0.x; o0.y += r0.y;
                o1.x += r1.x; o1.y += r1.y;
            }
            *(float2*)(C + (size_t)row * HIDC + col)       = o0;
            *(float2*)(C + (size_t)(row + 8) * HIDC + col) = o1;
        }
    }
}

__global__ __launch_bounds__(256, 2) void qkv_gemm(const float* __restrict__ H,
    const float* __restrict__ Wq, const float* __restrict__ bq,
    const float* __restrict__ Wk, const float* __restrict__ bk,
    const float* __restrict__ Wv, const float* __restrict__ bv)
{
    const float* W;
    const float* bias;
    float* out;
    if (blockIdx.z == 0)      { W = Wq; bias = bq; out = g_q; }
    else if (blockIdx.z == 1) { W = Wk; bias = bk; out = g_k; }
    else                      { W = Wv; bias = bv; out = g_v; }
    gemm_tc_body(H, W, bias, nullptr, out);
}

__global__ __launch_bounds__(256, 2) void o_gemm(const float* __restrict__ Wo,
    const float* __restrict__ bo, const float* __restrict__ H)
{
    gemm_tc_body(g_ctx, Wo, bo, H, g_x);
}

// ---------------------------------------------------------------------------
// Tensor-core fused attention. Per block: (b, h, 32 q-rows). 2xFP16.
//  Phase 1: S = (Q K^T + bias)/sqrt(32); Q split hi/lo, K single fp16
//  Phase 2: exact softmax; write probs; normalized P back to S
//  Phase 3: ctx^T = V^T P^T; V single fp16 (from fp32 smem), P split hi/lo
// ---------------------------------------------------------------------------
constexpr int SST  = 1032;  // S row stride (floats)
constexpr int KSTB = 20;    // fp16-word row stride (16 used)

constexpr int OFF_S  = 0;
constexpr int OFF_KH = 33024;               // phase1 K words / phase3 V fp32 (256*36) / red
constexpr int OFF_KL = OFF_KH + 8448;       // (unused in phase 1; part of V/red regions)
constexpr int OFF_QH = OFF_KL + 8448;
constexpr int OFF_QL = OFF_QH + 1056;
constexpr int OFF_BS = OFF_QL + 1056;
constexpr int ATTN_FLOATS = OFF_BS + 1056;  // 53088
constexpr size_t ATTN_SMEM_BYTES = (size_t)ATTN_FLOATS * sizeof(float);

__global__ __launch_bounds__(256, 1) void attn_kernel(const float* __restrict__ dist_emb,
                                                      float* __restrict__ probs_out)
{
    extern __shared__ float sm[];
    float*    S  = sm + OFF_S;
    uint32_t* kh = (uint32_t*)(sm + OFF_KH);
    uint32_t* qh = (uint32_t*)(sm + OFF_QH);
    uint32_t* ql = (uint32_t*)(sm + OFF_QL);
    float*    bs = sm + OFF_BS;

    const int t   = threadIdx.x;
    const int q0  = blockIdx.x * 32;
    const int h   = blockIdx.y;
    const int b   = blockIdx.z;
    const int wid = t >> 5, lane = t & 31;
    const int g   = lane >> 2, t4 = lane & 3;

    const size_t bh_off = (size_t)b * SEQ * HIDC + (size_t)h * HDC;
    const float* Qb = g_q + bh_off;
    const float* Kb = g_k + bh_off;
    const float* Vb = g_v + bh_off;

    for (int r = t; r < 1055; r += 256)
        bs[r] = dist_emb[(size_t)(q0 + r) * HDC + h];

    // stage Q tile (32x32) as fp16 hi/lo pair-words
    {
        const int row = t >> 3, c4 = (t & 7) * 4, w2 = (t & 7) * 2;
        float4 v = *(const float4*)(Qb + (size_t)(q0 + row) * HIDC + c4);
        uint32_t h0, l0, h1, l1;
        cvt_pair_h(v.x, v.y, h0, l0);
        cvt_pair_h(v.z, v.w, h1, l1);
        qh[row * KSTB + w2]     = h0;
        qh[row * KSTB + w2 + 1] = h1;
        ql[row * KSTB + w2]     = l0;
        ql[row * KSTB + w2 + 1] = l1;
    }
    __syncthreads();

    uint32_t qfh[2][2][4], qfl[2][2][4];
#pragma unroll
    for (int mf = 0; mf < 2; mf++)
#pragma unroll
        for (int ks = 0; ks < 2; ks++) {
            const int r0 = (mf * 16 + g) * KSTB;
            const int r1 = r0 + 8 * KSTB;
            const int k0 = ks * 8 + t4;
            qfh[mf][ks][0] = qh[r0 + k0];
            qfh[mf][ks][1] = qh[r1 + k0];
            qfh[mf][ks][2] = qh[r0 + k0 + 4];
            qfh[mf][ks][3] = qh[r1 + k0 + 4];
            qfl[mf][ks][0] = ql[r0 + k0];
            qfl[mf][ks][1] = ql[r1 + k0];
            qfl[mf][ks][2] = ql[r0 + k0 + 4];
            qfl[mf][ks][3] = ql[r1 + k0 + 4];
        }

    const float scale = 0.17677669529663688f;

    // ---- Phase 1: S = (Q K^T + bias) * scale ----
    for (int c = 0; c < 4; c++) {
        __syncthreads();
        // stage K chunk (256x32) as SINGLE fp16 words
#pragma unroll
        for (int p = 0; p < 8; p++) {
            const int row = p * 32 + (t >> 3), c4 = (t & 7) * 4, w2 = (t & 7) * 2;
            float4 v = *(const float4*)(Kb + (size_t)(c * 256 + row) * HIDC + c4);
            kh[row * KSTB + w2]     = cvt_h2(v.x, v.y);
            kh[row * KSTB + w2 + 1] = cvt_h2(v.z, v.w);
        }
        __syncthreads();

        const int kw = wid * 32;
#pragma unroll
        for (int nf = 0; nf < 4; nf++) {
            uint32_t bhh[2][2];
#pragma unroll
            for (int ks = 0; ks < 2; ks++) {
                const int n = (kw + nf * 8 + g) * KSTB + ks * 8 + t4;
                bhh[ks][0] = kh[n]; bhh[ks][1] = kh[n + 4];
            }
#pragma unroll
            for (int mf = 0; mf < 2; mf++) {
                float acc[4] = {0.f, 0.f, 0.f, 0.f};
#pragma unroll
                for (int ks = 0; ks < 2; ks++) {
                    mma_f16(acc, qfh[mf][ks], bhh[ks]);
                    mma_f16(acc, qfl[mf][ks], bhh[ks]);
                }
                const int row0 = mf * 16 + g;
                const int row1 = row0 + 8;
                const int col  = c * 256 + kw + nf * 8 + 2 * t4;
                float2 s0, s1;
                s0.x = (acc[0] + bs[row0 - col + 1023]) * scale;
                s0.y = (acc[1] + bs[row0 - col + 1022]) * scale;
                s1.x = (acc[2] + bs[row1 - col + 1023]) * scale;
                s1.y = (acc[3] + bs[row1 - col + 1022]) * scale;
                *(float2*)&S[row0 * SST + col] = s0;
                *(float2*)&S[row1 * SST + col] = s1;
            }
        }
    }
    __syncthreads();

    // ---- Phase 2: softmax; write probs; normalized P back to S ----
    {
        float* pb = probs_out + ((size_t)(b * NHC + h) * SEQ + q0) * SEQ;
        for (int rr = 0; rr < 4; rr++) {
            const int r = wid + 8 * rr;
            float* row = S + r * SST;
            float mx = -1e30f;
            for (int i = lane; i < 1024; i += 32) mx = fmaxf(mx, row[i]);
#pragma unroll
            for (int o = 16; o > 0; o >>= 1)
                mx = fmaxf(mx, __shfl_xor_sync(0xffffffffu, mx, o));
            float sum = 0.f;
            for (int i = lane; i < 1024; i += 32) {
                float e = __expf(row[i] - mx);
                row[i] = e;
                sum += e;
            }
#pragma unroll
            for (int o = 16; o > 0; o >>= 1)
                sum += __shfl_xor_sync(0xffffffffu, sum, o);
            const float inv = 1.f / sum;
            float* pr = pb + (size_t)r * SEQ;
            for (int i = lane; i < 1024; i += 32) {
                float p = row[i] * inv;
                row[i] = p;
                pr[i]  = p;
            }
        }
    }

    // ---- Phase 3: ctx^T = V^T @ P^T via 2xFP16 (m=dim, n=q, k=key) ----
    float* kvf = sm + OFF_KH;  // 256 x 36 fp32 V chunk

    float acc[2][4][4];
#pragma unroll
    for (int mf = 0; mf < 2; mf++)
#pragma unroll
        for (int nf = 0; nf < 4; nf++)
#pragma unroll
            for (int r = 0; r < 4; r++) acc[mf][nf][r] = 0.f;

    for (int c = 0; c < 4; c++) {
        __syncthreads();
#pragma unroll
        for (int p = 0; p < 8; p++) {
            const int row = p * 32 + (t >> 3), c4 = (t & 7) * 4;
            *(float4*)&kvf[row * 36 + c4] =
                *(const float4*)(Vb + (size_t)(c * 256 + row) * HIDC + c4);
        }
        __syncthreads();

        const int kw = wid * 32;
#pragma unroll
        for (int ks = 0; ks < 2; ks++) {
            const int base = kw + ks * 16;
            const int k0   = base + 2 * t4;
            // A fragments: single fp16; words pair adjacent keys
            uint32_t av[2][4];
#pragma unroll
            for (int mf = 0; mf < 2; mf++) {
                const int d = mf * 16 + g;
                av[mf][0] = cvt_h2(kvf[k0 * 36 + d],           kvf[(k0 + 1) * 36 + d]);
                av[mf][1] = cvt_h2(kvf[k0 * 36 + d + 8],       kvf[(k0 + 1) * 36 + d + 8]);
                av[mf][2] = cvt_h2(kvf[(k0 + 8) * 36 + d],     kvf[(k0 + 9) * 36 + d]);
                av[mf][3] = cvt_h2(kvf[(k0 + 8) * 36 + d + 8], kvf[(k0 + 9) * 36 + d + 8]);
            }
            const int gbase = c * 256 + base;
#pragma unroll
            for (int nf = 0; nf < 4; nf++) {
                const int q = nf * 8 + g;
                float2 p0 = *(const float2*)&S[q * SST + gbase + 2 * t4];
                float2 p1 = *(const float2*)&S[q * SST + gbase + 8 + 2 * t4];
                uint32_t bh2[2], bl2[2];
                cvt_pair_h(p0.x, p0.y, bh2[0], bl2[0]);
                cvt_pair_h(p1.x, p1.y, bh2[1], bl2[1]);
#pragma unroll
                for (int mf = 0; mf < 2; mf++) {
                    mma_f16(acc[mf][nf], av[mf], bh2);
                    mma_f16(acc[mf][nf], av[mf], bl2);
                }
            }
        }
    }
    __syncthreads();

    // cross-warp reduction of partial ctx
    float* red = sm + OFF_KH;
#pragma unroll
    for (int mf = 0; mf < 2; mf++)
#pragma unroll
        for (int nf = 0; nf < 4; nf++) {
            const int d = mf * 16 + g;
            const int q = nf * 8 + 2 * t4;
            float* rw = red + wid * 1056;
            rw[q * 33 + d]           = acc[mf][nf][0];
            rw[(q + 1) * 33 + d]     = acc[mf][nf][1];
            rw[q * 33 + d + 8]       = acc[mf][nf][2];
            rw[(q + 1) * 33 + d + 8] = acc[mf][nf][3];
        }
    __syncthreads();

#pragma unroll
    for (int i = 0; i < 4; i++) {
        const int idx = t + i * 256;
        const int q = idx >> 5, d = idx & 31;
        float s = 0.f;
#pragma unroll
        for (int w = 0; w < 8; w++) s += red[w * 1056 + q * 33 + d];
        g_ctx[(size_t)(b * SEQ + q0 + q) * HIDC + h * HDC + d] = s;
    }
}

// ---------------------------------------------------------------------------
// LayerNorm (unchanged)
// ---------------------------------------------------------------------------
__global__ void ln_kernel(const float* __restrict__ gamma,
                          const float* __restrict__ beta,
                          float* __restrict__ out)
{
    __shared__ float red[8];
    const int row = blockIdx.x, t = threadIdx.x;
    const int w = t >> 5, lane = t & 31;

    float4 v = *((const float4*)(g_x + (size_t)row * HIDC) + t);
    float s = v.x + v.y + v.z + v.w;
#pragma unroll
    for (int o = 16; o > 0; o >>= 1) s += __shfl_xor_sync(0xffffffffu, s, o);
    if (lane == 0) red[w] = s;
    __syncthreads();
    if (t == 0) {
        float tt = 0.f;
#pragma unroll
        for (int i = 0; i < 8; i++) tt += red[i];
        red[0] = tt;
    }
    __syncthreads();
    const float mu = red[0] * (1.f / 1024.f);
    __syncthreads();

    float dx = v.x - mu, dy = v.y - mu, dz = v.z - mu, dw = v.w - mu;
    float sq = dx * dx + dy * dy + dz * dz + dw * dw;
#pragma unroll
    for (int o = 16; o > 0; o >>= 1) sq += __shfl_xor_sync(0xffffffffu, sq, o);
    if (lane == 0) red[w] = sq;
    __syncthreads();
    if (t == 0) {
        float tt = 0.f;
#pragma unroll
        for (int i = 0; i < 8; i++) tt += red[i];
        red[0] = tt;
    }
    __syncthreads();
    const float inv = rsqrtf(red[0] * (1.f / 1024.f) + 1e-12f);

    float4 g  = *((const float4*)gamma + t);
    float4 bt = *((const float4*)beta + t);
    float4 o4;
    o4.x = dx * inv * g.x + bt.x;
    o4.y = dy * inv * g.y + bt.y;
    o4.z = dz * inv * g.z + bt.z;
    o4.w = dw * inv * g.w + bt.w;
    *((float4*)(out + (size_t)row * HIDC) + t) = o4;
}

// ---------------------------------------------------------------------------
// Launch
// ---------------------------------------------------------------------------
extern "C" void kernel_launch(void* const* d_in, const int* in_sizes, int n_in,
                              void* d_out, int out_size)
{
    (void)in_sizes; (void)n_in; (void)out_size;
    const float* hidden = (const float*)d_in[0];
    const float* Wq = (const float*)d_in[1];
    const float* bq = (const float*)d_in[2];
    const float* Wk = (const float*)d_in[3];
    const float* bk = (const float*)d_in[4];
    const float* Wv = (const float*)d_in[5];
    const float* bv = (const float*)d_in[6];
    const float* Wo = (const float*)d_in[7];
    const float* bo = (const float*)d_in[8];
    const float* gamma = (const float*)d_in[9];
    const float* beta  = (const float*)d_in[10];
    const float* dist  = (const float*)d_in[11];

    float* out   = (float*)d_out;
    float* probs = out + (size_t)BATCH * SEQ * HIDC;

    cudaFuncSetAttribute(attn_kernel, cudaFuncAttributeMaxDynamicSharedMemorySize,
                         (int)ATTN_SMEM_BYTES);

    qkv_gemm<<<dim3(8, 32, 3), 256>>>(hidden, Wq, bq, Wk, bk, Wv, bv);
    attn_kernel<<<dim3(32, 32, 4), 256, ATTN_SMEM_BYTES>>>(dist, probs);
    o_gemm<<<dim3(8, 32, 1), 256>>>(Wo, bo, hidden);
    ln_kernel<<<MR, 256>>>(gamma, beta, out);
}

// round 16
// speedup vs baseline: 1.5424x; 1.1316x over previous
#include <cuda_runtime.h>
#include <cuda_fp16.h>
#include <cstdint>
#include <cstddef>

// Problem constants
constexpr int SEQ   = 1024;
constexpr int HIDC  = 1024;
constexpr int NHC   = 32;
constexpr int HDC   = 32;
constexpr int BATCH = 4;
constexpr int MR    = BATCH * SEQ;   // 4096 rows

// Scratch
__device__ float g_q[(size_t)MR * HIDC];
__device__ float g_k[(size_t)MR * HIDC];
__device__ float g_v[(size_t)MR * HIDC];
__device__ float g_ctx[(size_t)MR * HIDC];
__device__ float g_x[(size_t)MR * HIDC];

__device__ __forceinline__ void mma_f16(float* c, const uint32_t* a, const uint32_t* b) {
    asm volatile(
        "mma.sync.aligned.m16n8k16.row.col.f32.f16.f16.f32 "
        "{%0,%1,%2,%3}, {%4,%5,%6,%7}, {%8,%9}, {%0,%1,%2,%3};\n"
        : "+f"(c[0]), "+f"(c[1]), "+f"(c[2]), "+f"(c[3])
        : "r"(a[0]), "r"(a[1]), "r"(a[2]), "r"(a[3]), "r"(b[0]), "r"(b[1]));
}

// f32 pair -> single fp16x2 word.
__device__ __forceinline__ uint32_t cvt_h2(float x, float y) {
    __half2 h = __floats2half2_rn(x, y);
    return *reinterpret_cast<uint32_t*>(&h);
}

// ---------------------------------------------------------------------------
// FP16 tensor-core GEMM: C = A @ B^T + bias (+resid); both operands single
// fp16 (fp32 accumulate). CTA tile 128x128x16, 8 warps (2M x 4N), 2-stage
// smem ping-pong.
// ---------------------------------------------------------------------------
constexpr int LDB = 12;

__device__ __forceinline__ void gemm_tc_body(const float* __restrict__ A,
                                             const float* __restrict__ B,
                                             const float* __restrict__ bias,
                                             const float* __restrict__ resid,
                                             float* __restrict__ C)
{
    __shared__ uint32_t sA[2][128 * LDB];
    __shared__ uint32_t sB[2][128 * LDB];

    const int t    = threadIdx.x;
    const int m0   = blockIdx.y * 128;
    const int n0   = blockIdx.x * 128;
    const int wid  = t >> 5, lane = t & 31;
    const int wm   = wid & 1, wn = wid >> 1;
    const int g    = lane >> 2, t4 = lane & 3;

    const int lr = t >> 2;             // 0..63
    const int lw = (t & 3) * 2;        // word offset 0,2,4,6
    const float* Ap = A + (size_t)(m0 + lr) * HIDC + (t & 3) * 4;
    const float* Bp = B + (size_t)(n0 + lr) * HIDC + (t & 3) * 4;

    float acc[4][4][4];
#pragma unroll
    for (int i = 0; i < 4; i++)
#pragma unroll
        for (int j = 0; j < 4; j++)
#pragma unroll
            for (int r = 0; r < 4; r++) acc[i][j][r] = 0.f;

    float4 ra0, ra1, rb0, rb1;
    auto gload = [&](int kt) {
        const float* a = Ap + kt * 16;
        const float* b = Bp + kt * 16;
        ra0 = *(const float4*)(a);
        ra1 = *(const float4*)(a + (size_t)64 * HIDC);
        rb0 = *(const float4*)(b);
        rb1 = *(const float4*)(b + (size_t)64 * HIDC);
    };
    auto sts = [&](int st) {
        sA[st][lr * LDB + lw]            = cvt_h2(ra0.x, ra0.y);
        sA[st][lr * LDB + lw + 1]        = cvt_h2(ra0.z, ra0.w);
        sA[st][(lr + 64) * LDB + lw]     = cvt_h2(ra1.x, ra1.y);
        sA[st][(lr + 64) * LDB + lw + 1] = cvt_h2(ra1.z, ra1.w);
        sB[st][lr * LDB + lw]            = cvt_h2(rb0.x, rb0.y);
        sB[st][lr * LDB + lw + 1]        = cvt_h2(rb0.z, rb0.w);
        sB[st][(lr + 64) * LDB + lw]     = cvt_h2(rb1.x, rb1.y);
        sB[st][(lr + 64) * LDB + lw + 1] = cvt_h2(rb1.z, rb1.w);
    };

    gload(0);
    sts(0);
    __syncthreads();

    for (int kt = 0; kt < HIDC / 16; kt++) {
        const int st = kt & 1;
        if (kt + 1 < HIDC / 16) gload(kt + 1);

        uint32_t bfr[4][2];
#pragma unroll
        for (int nf = 0; nf < 4; nf++) {
            const int n = (wn * 32 + nf * 8 + g) * LDB;
            bfr[nf][0] = sB[st][n + t4];
            bfr[nf][1] = sB[st][n + t4 + 4];
        }
#pragma unroll
        for (int mf = 0; mf < 4; mf++) {
            const int m = (wm * 64 + mf * 16 + g) * LDB;
            uint32_t af[4];
            af[0] = sA[st][m + t4];
            af[1] = sA[st][m + 8 * LDB + t4];
            af[2] = sA[st][m + t4 + 4];
            af[3] = sA[st][m + 8 * LDB + t4 + 4];
#pragma unroll
            for (int nf = 0; nf < 4; nf++)
                mma_f16(acc[mf][nf], af, bfr[nf]);
        }

        if (kt + 1 < HIDC / 16) {
            sts((kt + 1) & 1);
            __syncthreads();
        }
    }

#pragma unroll
    for (int mf = 0; mf < 4; mf++) {
#pragma unroll
        for (int nf = 0; nf < 4; nf++) {
            const int row = m0 + wm * 64 + mf * 16 + g;
            const int col = n0 + wn * 32 + nf * 8 + t4 * 2;
            float2 bb = *(const float2*)(bias + col);
            float2 o0, o1;
            o0.x = acc[mf][nf][0] + bb.x;
            o0.y = acc[mf][nf][1] + bb.y;
            o1.x = acc[mf][nf][2] + bb.x;
            o1.y = acc[mf][nf][3] + bb.y;
            if (resid != nullptr) {
                float2 r0 = *(const float2*)(resid + (size_t)row * HIDC + col);
                float2 r1 = *(const float2*)(resid + (size_t)(row + 8) * HIDC + col);
                o0.x += r0.x; o0.y += r0.y;
                o1.x += r1.x; o1.y += r1.y;
            }
            *(float2*)(C + (size_t)row * HIDC + col)       = o0;
            *(float2*)(C + (size_t)(row + 8) * HIDC + col) = o1;
        }
    }
}

__global__ __launch_bounds__(256, 2) void qkv_gemm(const float* __restrict__ H,
    const float* __restrict__ Wq, const float* __restrict__ bq,
    const float* __restrict__ Wk, const float* __restrict__ bk,
    const float* __restrict__ Wv, const float* __restrict__ bv)
{
    const float* W;
    const float* bias;
    float* out;
    if (blockIdx.z == 0)      { W = Wq; bias = bq; out = g_q; }
    else if (blockIdx.z == 1) { W = Wk; bias = bk; out = g_k; }
    else                      { W = Wv; bias = bv; out = g_v; }
    gemm_tc_body(H, W, bias, nullptr, out);
}

__global__ __launch_bounds__(256, 2) void o_gemm(const float* __restrict__ Wo,
    const float* __restrict__ bo, const float* __restrict__ H)
{
    gemm_tc_body(g_ctx, Wo, bo, H, g_x);
}

// ---------------------------------------------------------------------------
// Tensor-core fused attention. Per block: (b, h, 32 q-rows). Single FP16.
//  Phase 1: S = (Q K^T + bias)/sqrt(32); Q and K single fp16
//  Phase 2: exact softmax; write probs; keep UNNORMALIZED e in S, inv in smem
//  Phase 3: ctx^T = V^T E^T; final reduction scales by inv[q]
// ---------------------------------------------------------------------------
constexpr int SST  = 1032;  // S row stride (floats)
constexpr int KSTB = 20;    // fp16-word row stride (16 used)

constexpr int OFF_S  = 0;
constexpr int OFF_KH = 33024;               // phase1 K words / phase3 V fp32 (256*36) / red
constexpr int OFF_KL = OFF_KH + 8448;
constexpr int OFF_QH = OFF_KL + 8448;
constexpr int OFF_QL = OFF_QH + 1056;       // free (Q not split); kept for layout
constexpr int OFF_BS = OFF_QL + 1056;
constexpr int OFF_IV = OFF_BS + 1056;       // inv[32]
constexpr int ATTN_FLOATS = OFF_IV + 32;    // 53120
constexpr size_t ATTN_SMEM_BYTES = (size_t)ATTN_FLOATS * sizeof(float);

__global__ __launch_bounds__(256, 1) void attn_kernel(const float* __restrict__ dist_emb,
                                                      float* __restrict__ probs_out)
{
    extern __shared__ float sm[];
    float*    S   = sm + OFF_S;
    uint32_t* kh  = (uint32_t*)(sm + OFF_KH);
    uint32_t* qh  = (uint32_t*)(sm + OFF_QH);
    float*    bs  = sm + OFF_BS;
    float*    siv = sm + OFF_IV;

    const int t   = threadIdx.x;
    const int q0  = blockIdx.x * 32;
    const int h   = blockIdx.y;
    const int b   = blockIdx.z;
    const int wid = t >> 5, lane = t & 31;
    const int g   = lane >> 2, t4 = lane & 3;

    const size_t bh_off = (size_t)b * SEQ * HIDC + (size_t)h * HDC;
    const float* Qb = g_q + bh_off;
    const float* Kb = g_k + bh_off;
    const float* Vb = g_v + bh_off;

    for (int r = t; r < 1055; r += 256)
        bs[r] = dist_emb[(size_t)(q0 + r) * HDC + h];

    // stage Q tile (32x32) as single fp16 words
    {
        const int row = t >> 3, c4 = (t & 7) * 4, w2 = (t & 7) * 2;
        float4 v = *(const float4*)(Qb + (size_t)(q0 + row) * HIDC + c4);
        qh[row * KSTB + w2]     = cvt_h2(v.x, v.y);
        qh[row * KSTB + w2 + 1] = cvt_h2(v.z, v.w);
    }
    __syncthreads();

    uint32_t qf[2][2][4];
#pragma unroll
    for (int mf = 0; mf < 2; mf++)
#pragma unroll
        for (int ks = 0; ks < 2; ks++) {
            const int r0 = (mf * 16 + g) * KSTB;
            const int r1 = r0 + 8 * KSTB;
            const int k0 = ks * 8 + t4;
            qf[mf][ks][0] = qh[r0 + k0];
            qf[mf][ks][1] = qh[r1 + k0];
            qf[mf][ks][2] = qh[r0 + k0 + 4];
            qf[mf][ks][3] = qh[r1 + k0 + 4];
        }

    const float scale = 0.17677669529663688f;

    // ---- Phase 1: S = (Q K^T + bias) * scale ----
    for (int c = 0; c < 4; c++) {
        __syncthreads();
#pragma unroll
        for (int p = 0; p < 8; p++) {
            const int row = p * 32 + (t >> 3), c4 = (t & 7) * 4, w2 = (t & 7) * 2;
            float4 v = *(const float4*)(Kb + (size_t)(c * 256 + row) * HIDC + c4);
            kh[row * KSTB + w2]     = cvt_h2(v.x, v.y);
            kh[row * KSTB + w2 + 1] = cvt_h2(v.z, v.w);
        }
        __syncthreads();

        const int kw = wid * 32;
#pragma unroll
        for (int nf = 0; nf < 4; nf++) {
            uint32_t bhh[2][2];
#pragma unroll
            for (int ks = 0; ks < 2; ks++) {
                const int n = (kw + nf * 8 + g) * KSTB + ks * 8 + t4;
                bhh[ks][0] = kh[n]; bhh[ks][1] = kh[n + 4];
            }
#pragma unroll
            for (int mf = 0; mf < 2; mf++) {
                float acc[4] = {0.f, 0.f, 0.f, 0.f};
#pragma unroll
                for (int ks = 0; ks < 2; ks++)
                    mma_f16(acc, qf[mf][ks], bhh[ks]);
                const int row0 = mf * 16 + g;
                const int row1 = row0 + 8;
                const int col  = c * 256 + kw + nf * 8 + 2 * t4;
                float2 s0, s1;
                s0.x = (acc[0] + bs[row0 - col + 1023]) * scale;
                s0.y = (acc[1] + bs[row0 - col + 1022]) * scale;
                s1.x = (acc[2] + bs[row1 - col + 1023]) * scale;
                s1.y = (acc[3] + bs[row1 - col + 1022]) * scale;
                *(float2*)&S[row0 * SST + col] = s0;
                *(float2*)&S[row1 * SST + col] = s1;
            }
        }
    }
    __syncthreads();

    // ---- Phase 2: softmax; write probs; keep e in S; save inv[q] ----
    {
        float* pb = probs_out + ((size_t)(b * NHC + h) * SEQ + q0) * SEQ;
        for (int rr = 0; rr < 4; rr++) {
            const int r = wid + 8 * rr;
            float* row = S + r * SST;
            float mx = -1e30f;
            for (int i = lane; i < 1024; i += 32) mx = fmaxf(mx, row[i]);
#pragma unroll
            for (int o = 16; o > 0; o >>= 1)
                mx = fmaxf(mx, __shfl_xor_sync(0xffffffffu, mx, o));
            float sum = 0.f;
            for (int i = lane; i < 1024; i += 32) {
                float e = __expf(row[i] - mx);
                row[i] = e;
                sum += e;
            }
#pragma unroll
            for (int o = 16; o > 0; o >>= 1)
                sum += __shfl_xor_sync(0xffffffffu, sum, o);
            const float inv = 1.f / sum;
            if (lane == 0) siv[r] = inv;
            float* pr = pb + (size_t)r * SEQ;
            for (int i = lane; i < 1024; i += 32)
                pr[i] = row[i] * inv;        // probs to gmem; S keeps e
        }
    }

    // ---- Phase 3: ctx^T = V^T @ E^T via FP16 (m=dim, n=q, k=key) ----
    float* kvf = sm + OFF_KH;  // 256 x 36 fp32 V chunk

    float acc[2][4][4];
#pragma unroll
    for (int mf = 0; mf < 2; mf++)
#pragma unroll
        for (int nf = 0; nf < 4; nf++)
#pragma unroll
            for (int r = 0; r < 4; r++) acc[mf][nf][r] = 0.f;

    for (int c = 0; c < 4; c++) {
        __syncthreads();
#pragma unroll
        for (int p = 0; p < 8; p++) {
            const int row = p * 32 + (t >> 3), c4 = (t & 7) * 4;
            *(float4*)&kvf[row * 36 + c4] =
                *(const float4*)(Vb + (size_t)(c * 256 + row) * HIDC + c4);
        }
        __syncthreads();

        const int kw = wid * 32;
#pragma unroll
        for (int ks = 0; ks < 2; ks++) {
            const int base = kw + ks * 16;
            const int k0   = base + 2 * t4;
            uint32_t av[2][4];
#pragma unroll
            for (int mf = 0; mf < 2; mf++) {
                const int d = mf * 16 + g;
                av[mf][0] = cvt_h2(kvf[k0 * 36 + d],           kvf[(k0 + 1) * 36 + d]);
                av[mf][1] = cvt_h2(kvf[k0 * 36 + d + 8],       kvf[(k0 + 1) * 36 + d + 8]);
                av[mf][2] = cvt_h2(kvf[(k0 + 8) * 36 + d],     kvf[(k0 + 9) * 36 + d]);
                av[mf][3] = cvt_h2(kvf[(k0 + 8) * 36 + d + 8], kvf[(k0 + 9) * 36 + d + 8]);
            }
            const int gbase = c * 256 + base;
#pragma unroll
            for (int nf = 0; nf < 4; nf++) {
                const int q = nf * 8 + g;
                float2 p0 = *(const float2*)&S[q * SST + gbase + 2 * t4];
                float2 p1 = *(const float2*)&S[q * SST + gbase + 8 + 2 * t4];
                uint32_t bf2[2];
                bf2[0] = cvt_h2(p0.x, p0.y);
                bf2[1] = cvt_h2(p1.x, p1.y);
#pragma unroll
                for (int mf = 0; mf < 2; mf++)
                    mma_f16(acc[mf][nf], av[mf], bf2);
            }
        }
    }
    __syncthreads();

    // cross-warp reduction of partial ctx; scale by inv[q] at the end
    float* red = sm + OFF_KH;
#pragma unroll
    for (int mf = 0; mf < 2; mf++)
#pragma unroll
        for (int nf = 0; nf < 4; nf++) {
            const int d = mf * 16 + g;
            const int q = nf * 8 + 2 * t4;
            float* rw = red + wid * 1056;
            rw[q * 33 + d]           = acc[mf][nf][0];
            rw[(q + 1) * 33 + d]     = acc[mf][nf][1];
            rw[q * 33 + d + 8]       = acc[mf][nf][2];
            rw[(q + 1) * 33 + d + 8] = acc[mf][nf][3];
        }
    __syncthreads();

#pragma unroll
    for (int i = 0; i < 4; i++) {
        const int idx = t + i * 256;
        const int q = idx >> 5, d = idx & 31;
        float s = 0.f;
#pragma unroll
        for (int w = 0; w < 8; w++) s += red[w * 1056 + q * 33 + d];
        g_ctx[(size_t)(b * SEQ + q0 + q) * HIDC + h * HDC + d] = s * siv[q];
    }
}

// ---------------------------------------------------------------------------
// LayerNorm (unchanged)
// ---------------------------------------------------------------------------
__global__ void ln_kernel(const float* __restrict__ gamma,
                          const float* __restrict__ beta,
                          float* __restrict__ out)
{
    __shared__ float red[8];
    const int row = blockIdx.x, t = threadIdx.x;
    const int w = t >> 5, lane = t & 31;

    float4 v = *((const float4*)(g_x + (size_t)row * HIDC) + t);
    float s = v.x + v.y + v.z + v.w;
#pragma unroll
    for (int o = 16; o > 0; o >>= 1) s += __shfl_xor_sync(0xffffffffu, s, o);
    if (lane == 0) red[w] = s;
    __syncthreads();
    if (t == 0) {
        float tt = 0.f;
#pragma unroll
        for (int i = 0; i < 8; i++) tt += red[i];
        red[0] = tt;
    }
    __syncthreads();
    const float mu = red[0] * (1.f / 1024.f);
    __syncthreads();

    float dx = v.x - mu, dy = v.y - mu, dz = v.z - mu, dw = v.w - mu;
    float sq = dx * dx + dy * dy + dz * dz + dw * dw;
#pragma unroll
    for (int o = 16; o > 0; o >>= 1) sq += __shfl_xor_sync(0xffffffffu, sq, o);
    if (lane == 0) red[w] = sq;
    __syncthreads();
    if (t == 0) {
        float tt = 0.f;
#pragma unroll
        for (int i = 0; i < 8; i++) tt += red[i];
        red[0] = tt;
    }
    __syncthreads();
    const float inv = rsqrtf(red[0] * (1.f / 1024.f) + 1e-12f);

    float4 g  = *((const float4*)gamma + t);
    float4 bt = *((const float4*)beta + t);
    float4 o4;
    o4.x = dx * inv * g.x + bt.x;
    o4.y = dy * inv * g.y + bt.y;
    o4.z = dz * inv * g.z + bt.z;
    o4.w = dw * inv * g.w + bt.w;
    *((float4*)(out + (size_t)row * HIDC) + t) = o4;
}

// ---------------------------------------------------------------------------
// Launch
// ---------------------------------------------------------------------------
extern "C" void kernel_launch(void* const* d_in, const int* in_sizes, int n_in,
                              void* d_out, int out_size)
{
    (void)in_sizes; (void)n_in; (void)out_size;
    const float* hidden = (const float*)d_in[0];
    const float* Wq = (const float*)d_in[1];
    const float* bq = (const float*)d_in[2];
    const float* Wk = (const float*)d_in[3];
    const float* bk = (const float*)d_in[4];
    const float* Wv = (const float*)d_in[5];
    const float* bv = (const float*)d_in[6];
    const float* Wo = (const float*)d_in[7];
    const float* bo = (const float*)d_in[8];
    const float* gamma = (const float*)d_in[9];
    const float* beta  = (const float*)d_in[10];
    const float* dist  = (const float*)d_in[11];

    float* out   = (float*)d_out;
    float* probs = out + (size_t)BATCH * SEQ * HIDC;

    cudaFuncSetAttribute(attn_kernel, cudaFuncAttributeMaxDynamicSharedMemorySize,
                         (int)ATTN_SMEM_BYTES);

    qkv_gemm<<<dim3(8, 32, 3), 256>>>(hidden, Wq, bq, Wk, bk, Wv, bv);
    attn_kernel<<<dim3(32, 32, 4), 256, ATTN_SMEM_BYTES>>>(dist, probs);
    o_gemm<<<dim3(8, 32, 1), 256>>>(Wo, bo, hidden);
    ln_kernel<<<MR, 256>>>(gamma, beta, out);
}

// round 17
// speedup vs baseline: 1.6226x; 1.0520x over previous
#include <cuda_runtime.h>
#include <cuda_fp16.h>
#include <cstdint>
#include <cstddef>

// Problem constants
constexpr int SEQ   = 1024;
constexpr int HIDC  = 1024;
constexpr int NHC   = 32;
constexpr int HDC   = 32;
constexpr int BATCH = 4;
constexpr int MR    = BATCH * SEQ;   // 4096 rows
constexpr int WR    = HIDC / 2;      // 512 fp16x2 words per row

// Scratch (fp16x2 word buffers pack pairs along the HID/k dimension)
__device__ uint32_t g_hw[(size_t)MR * WR];            // hidden fp16
__device__ uint32_t g_wf[(size_t)4 * HIDC * WR];      // Wq,Wk,Wv,Wo fp16
__device__ uint32_t g_qw[(size_t)MR * WR];            // Q fp16
__device__ uint32_t g_kw[(size_t)MR * WR];            // K fp16
__device__ uint32_t g_cw[(size_t)MR * WR];            // ctx fp16
__device__ float    g_v[(size_t)MR * HIDC];           // V fp32
__device__ float    g_x[(size_t)MR * HIDC];           // attn_out + resid

__device__ __forceinline__ void mma_f16(float* c, const uint32_t* a, const uint32_t* b) {
    asm volatile(
        "mma.sync.aligned.m16n8k16.row.col.f32.f16.f16.f32 "
        "{%0,%1,%2,%3}, {%4,%5,%6,%7}, {%8,%9}, {%0,%1,%2,%3};\n"
        : "+f"(c[0]), "+f"(c[1]), "+f"(c[2]), "+f"(c[3])
        : "r"(a[0]), "r"(a[1]), "r"(a[2]), "r"(a[3]), "r"(b[0]), "r"(b[1]));
}

__device__ __forceinline__ uint32_t cvt_h2(float x, float y) {
    __half2 h = __floats2half2_rn(x, y);
    return *reinterpret_cast<uint32_t*>(&h);
}

// ---------------------------------------------------------------------------
// Prepass: fp32 -> fp16x2 words. Destination resolved IN DEVICE CODE
// (never pass __device__ symbols as kernel args — GB300 ATS silently
// writes the host shadow).
// ---------------------------------------------------------------------------
__global__ void cvt_kernel(const float* __restrict__ src, int which)
{
    uint32_t* d;
    const size_t WW = (size_t)HIDC * WR;
    if (which == 0) d = g_hw;
    else            d = g_wf + (size_t)(which - 1) * WW;
    const int i = blockIdx.x * blockDim.x + threadIdx.x;
    float4 v = ((const float4*)src)[i];
    ((uint2*)d)[i] = make_uint2(cvt_h2(v.x, v.y), cvt_h2(v.z, v.w));
}

// ---------------------------------------------------------------------------
// FP16 word-input GEMM: C = A @ B^T + bias; C fp32 (+resid) or fp16 words.
// CTA tile 128x128x16 (8 k-words), 8 warps (2M x 4N), 2-stage ping-pong.
// ---------------------------------------------------------------------------
constexpr int LDB = 12;

__device__ __forceinline__ void gemm_w_body(const uint32_t* __restrict__ Aw,
                                            const uint32_t* __restrict__ Bw,
                                            const float* __restrict__ bias,
                                            const float* __restrict__ resid,
                                            float* __restrict__ Cf,
                                            uint32_t* __restrict__ Cw)
{
    __shared__ uint32_t sA[2][128 * LDB];
    __shared__ uint32_t sB[2][128 * LDB];

    const int t    = threadIdx.x;
    const int m0   = blockIdx.y * 128;
    const int n0   = blockIdx.x * 128;
    const int wid  = t >> 5, lane = t & 31;
    const int wm   = wid & 1, wn = wid >> 1;
    const int g    = lane >> 2, t4 = lane & 3;

    const int lr = t >> 1;             // 0..127
    const int wq = (t & 1) * 4;        // word offset 0 or 4
    const uint32_t* Ap = Aw + (size_t)(m0 + lr) * WR + wq;
    const uint32_t* Bp = Bw + (size_t)(n0 + lr) * WR + wq;

    float acc[4][4][4];
#pragma unroll
    for (int i = 0; i < 4; i++)
#pragma unroll
        for (int j = 0; j < 4; j++)
#pragma unroll
            for (int r = 0; r < 4; r++) acc[i][j][r] = 0.f;

    uint4 pa, pb;
    auto gload = [&](int kt) {
        pa = *(const uint4*)(Ap + kt * 8);
        pb = *(const uint4*)(Bp + kt * 8);
    };
    auto sts = [&](int st) {
        *(uint4*)&sA[st][lr * LDB + wq] = pa;
        *(uint4*)&sB[st][lr * LDB + wq] = pb;
    };

    gload(0);
    sts(0);
    __syncthreads();

    constexpr int NKT = WR / 8;  // 64
    for (int kt = 0; kt < NKT; kt++) {
        const int st = kt & 1;
        if (kt + 1 < NKT) gload(kt + 1);

        uint32_t bfr[4][2];
#pragma unroll
        for (int nf = 0; nf < 4; nf++) {
            const int n = (wn * 32 + nf * 8 + g) * LDB;
            bfr[nf][0] = sB[st][n + t4];
            bfr[nf][1] = sB[st][n + t4 + 4];
        }
#pragma unroll
        for (int mf = 0; mf < 4; mf++) {
            const int m = (wm * 64 + mf * 16 + g) * LDB;
            uint32_t af[4];
            af[0] = sA[st][m + t4];
            af[1] = sA[st][m + 8 * LDB + t4];
            af[2] = sA[st][m + t4 + 4];
            af[3] = sA[st][m + 8 * LDB + t4 + 4];
#pragma unroll
            for (int nf = 0; nf < 4; nf++)
                mma_f16(acc[mf][nf], af, bfr[nf]);
        }

        if (kt + 1 < NKT) {
            sts((kt + 1) & 1);
            __syncthreads();
        }
    }

#pragma unroll
    for (int mf = 0; mf < 4; mf++) {
#pragma unroll
        for (int nf = 0; nf < 4; nf++) {
            const int row = m0 + wm * 64 + mf * 16 + g;
            const int col = n0 + wn * 32 + nf * 8 + t4 * 2;
            float2 bb = *(const float2*)(bias + col);
            float2 o0, o1;
            o0.x = acc[mf][nf][0] + bb.x;
            o0.y = acc[mf][nf][1] + bb.y;
            o1.x = acc[mf][nf][2] + bb.x;
            o1.y = acc[mf][nf][3] + bb.y;
            if (Cw != nullptr) {
                Cw[(size_t)row * WR + (col >> 1)]       = cvt_h2(o0.x, o0.y);
                Cw[(size_t)(row + 8) * WR + (col >> 1)] = cvt_h2(o1.x, o1.y);
            } else {
                if (resid != nullptr) {
                    float2 r0 = *(const float2*)(resid + (size_t)row * HIDC + col);
                    float2 r1 = *(const float2*)(resid + (size_t)(row + 8) * HIDC + col);
                    o0.x += r0.x; o0.y += r0.y;
                    o1.x += r1.x; o1.y += r1.y;
                }
                *(float2*)(Cf + (size_t)row * HIDC + col)       = o0;
                *(float2*)(Cf + (size_t)(row + 8) * HIDC + col) = o1;
            }
        }
    }
}

__global__ __launch_bounds__(256, 2) void qkv_gemm(
    const float* __restrict__ bq, const float* __restrict__ bk,
    const float* __restrict__ bv)
{
    const size_t WW = (size_t)HIDC * WR;
    const uint32_t* B = g_wf + (size_t)blockIdx.z * WW;
    const float* bias;
    float* Cf = nullptr;
    uint32_t* Cw = nullptr;
    if (blockIdx.z == 0)      { bias = bq; Cw = g_qw; }
    else if (blockIdx.z == 1) { bias = bk; Cw = g_kw; }
    else                      { bias = bv; Cf = g_v; }
    gemm_w_body(g_hw, B, bias, nullptr, Cf, Cw);
}

__global__ __launch_bounds__(256, 2) void o_gemm(const float* __restrict__ bo,
                                                 const float* __restrict__ H)
{
    const size_t WW = (size_t)HIDC * WR;
    gemm_w_body(g_cw, g_wf + 3 * WW, bo, H, g_x, nullptr);
}

// ---------------------------------------------------------------------------
// Tensor-core fused attention. Per block: (b, h, 32 q-rows). Single FP16.
//  Phase 1: S = (Q K^T + bias)/sqrt(32); Q/K pre-converted words (copy stage)
//  Phase 2: exact softmax; write probs; keep e in S; inv in smem
//  Phase 3: ctx^T = V^T E^T (V fp32, key-paired on the fly); scale by inv[q];
//           ctx emitted as fp16 d-pair words for o_gemm
// ---------------------------------------------------------------------------
constexpr int SST  = 1032;
constexpr int KSTB = 20;

constexpr int OFF_S  = 0;
constexpr int OFF_KH = 33024;               // K words (5120) / V fp32 (9216) / red (8448)
constexpr int OFF_KL = OFF_KH + 8448;
constexpr int OFF_QH = OFF_KL + 8448;       // Q words (640)
constexpr int OFF_BS = OFF_QH + 1056;
constexpr int OFF_IV = OFF_BS + 1056;       // inv[32]
constexpr int ATTN_FLOATS = OFF_IV + 32;    // 52064
constexpr size_t ATTN_SMEM_BYTES = (size_t)ATTN_FLOATS * sizeof(float);

__global__ __launch_bounds__(256, 1) void attn_kernel(const float* __restrict__ dist_emb,
                                                      float* __restrict__ probs_out)
{
    extern __shared__ float sm[];
    float*    S   = sm + OFF_S;
    uint32_t* kh  = (uint32_t*)(sm + OFF_KH);
    uint32_t* qh  = (uint32_t*)(sm + OFF_QH);
    float*    bs  = sm + OFF_BS;
    float*    siv = sm + OFF_IV;

    const int t   = threadIdx.x;
    const int q0  = blockIdx.x * 32;
    const int h   = blockIdx.y;
    const int b   = blockIdx.z;
    const int wid = t >> 5, lane = t & 31;
    const int g   = lane >> 2, t4 = lane & 3;

    const int brow = b * SEQ;
    const size_t wbase = (size_t)brow * WR + h * 16;   // word base for Q/K
    const float* Vb = g_v + (size_t)brow * HIDC + (size_t)h * HDC;

    for (int r = t; r < 1055; r += 256)
        bs[r] = dist_emb[(size_t)(q0 + r) * HDC + h];

    // stage Q tile (32 rows x 16 words) — pure copy
    {
        const int row = t >> 3, w2 = (t & 7) * 2;
        *(uint2*)&qh[row * KSTB + w2] =
            *(const uint2*)&g_qw[wbase + (size_t)(q0 + row) * WR + w2];
    }
    __syncthreads();

    uint32_t qf[2][2][4];
#pragma unroll
    for (int mf = 0; mf < 2; mf++)
#pragma unroll
        for (int ks = 0; ks < 2; ks++) {
            const int r0 = (mf * 16 + g) * KSTB;
            const int r1 = r0 + 8 * KSTB;
            const int k0 = ks * 8 + t4;
            qf[mf][ks][0] = qh[r0 + k0];
            qf[mf][ks][1] = qh[r1 + k0];
            qf[mf][ks][2] = qh[r0 + k0 + 4];
            qf[mf][ks][3] = qh[r1 + k0 + 4];
        }

    const float scale = 0.17677669529663688f;

    // ---- Phase 1: S = (Q K^T + bias) * scale ----
    for (int c = 0; c < 4; c++) {
        __syncthreads();
        // stage K chunk (256 rows x 16 words) — pure copy
#pragma unroll
        for (int p = 0; p < 4; p++) {
            const int row = p * 64 + (t >> 2), wq = (t & 3) * 4;
            *(uint4*)&kh[row * KSTB + wq] =
                *(const uint4*)&g_kw[wbase + (size_t)(c * 256 + row) * WR + wq];
        }
        __syncthreads();

        const int kw = wid * 32;
#pragma unroll
        for (int nf = 0; nf < 4; nf++) {
            uint32_t bhh[2][2];
#pragma unroll
            for (int ks = 0; ks < 2; ks++) {
                const int n = (kw + nf * 8 + g) * KSTB + ks * 8 + t4;
                bhh[ks][0] = kh[n]; bhh[ks][1] = kh[n + 4];
            }
#pragma unroll
            for (int mf = 0; mf < 2; mf++) {
                float acc[4] = {0.f, 0.f, 0.f, 0.f};
#pragma unroll
                for (int ks = 0; ks < 2; ks++)
                    mma_f16(acc, qf[mf][ks], bhh[ks]);
                const int row0 = mf * 16 + g;
                const int row1 = row0 + 8;
                const int col  = c * 256 + kw + nf * 8 + 2 * t4;
                float2 s0, s1;
                s0.x = (acc[0] + bs[row0 - col + 1023]) * scale;
                s0.y = (acc[1] + bs[row0 - col + 1022]) * scale;
                s1.x = (acc[2] + bs[row1 - col + 1023]) * scale;
                s1.y = (acc[3] + bs[row1 - col + 1022]) * scale;
                *(float2*)&S[row0 * SST + col] = s0;
                *(float2*)&S[row1 * SST + col] = s1;
            }
        }
    }
    __syncthreads();

    // ---- Phase 2: softmax; write probs; keep e in S; save inv[q] ----
    {
        float* pb = probs_out + ((size_t)(b * NHC + h) * SEQ + q0) * SEQ;
        for (int rr = 0; rr < 4; rr++) {
            const int r = wid + 8 * rr;
            float* row = S + r * SST;
            float mx = -1e30f;
            for (int i = lane; i < 1024; i += 32) mx = fmaxf(mx, row[i]);
#pragma unroll
            for (int o = 16; o > 0; o >>= 1)
                mx = fmaxf(mx, __shfl_xor_sync(0xffffffffu, mx, o));
            float sum = 0.f;
            for (int i = lane; i < 1024; i += 32) {
                float e = __expf(row[i] - mx);
                row[i] = e;
                sum += e;
            }
#pragma unroll
            for (int o = 16; o > 0; o >>= 1)
                sum += __shfl_xor_sync(0xffffffffu, sum, o);
            const float inv = 1.f / sum;
            if (lane == 0) siv[r] = inv;
            float* pr = pb + (size_t)r * SEQ;
            for (int i = lane; i < 1024; i += 32)
                pr[i] = row[i] * inv;
        }
    }

    // ---- Phase 3: ctx^T = V^T @ E^T via FP16 (m=dim, n=q, k=key) ----
    float* kvf = sm + OFF_KH;  // 256 x 36 fp32 V chunk

    float acc[2][4][4];
#pragma unroll
    for (int mf = 0; mf < 2; mf++)
#pragma unroll
        for (int nf = 0; nf < 4; nf++)
#pragma unroll
            for (int r = 0; r < 4; r++) acc[mf][nf][r] = 0.f;

    for (int c = 0; c < 4; c++) {
        __syncthreads();
#pragma unroll
        for (int p = 0; p < 8; p++) {
            const int row = p * 32 + (t >> 3), c4 = (t & 7) * 4;
            *(float4*)&kvf[row * 36 + c4] =
                *(const float4*)(Vb + (size_t)(c * 256 + row) * HIDC + c4);
        }
        __syncthreads();

        const int kw = wid * 32;
#pragma unroll
        for (int ks = 0; ks < 2; ks++) {
            const int base = kw + ks * 16;
            const int k0   = base + 2 * t4;
            uint32_t av[2][4];
#pragma unroll
            for (int mf = 0; mf < 2; mf++) {
                const int d = mf * 16 + g;
                av[mf][0] = cvt_h2(kvf[k0 * 36 + d],           kvf[(k0 + 1) * 36 + d]);
                av[mf][1] = cvt_h2(kvf[k0 * 36 + d + 8],       kvf[(k0 + 1) * 36 + d + 8]);
                av[mf][2] = cvt_h2(kvf[(k0 + 8) * 36 + d],     kvf[(k0 + 9) * 36 + d]);
                av[mf][3] = cvt_h2(kvf[(k0 + 8) * 36 + d + 8], kvf[(k0 + 9) * 36 + d + 8]);
            }
            const int gbase = c * 256 + base;
#pragma unroll
            for (int nf = 0; nf < 4; nf++) {
                const int q = nf * 8 + g;
                float2 p0 = *(const float2*)&S[q * SST + gbase + 2 * t4];
                float2 p1 = *(const float2*)&S[q * SST + gbase + 8 + 2 * t4];
                uint32_t bf2[2];
                bf2[0] = cvt_h2(p0.x, p0.y);
                bf2[1] = cvt_h2(p1.x, p1.y);
#pragma unroll
                for (int mf = 0; mf < 2; mf++)
                    mma_f16(acc[mf][nf], av[mf], bf2);
            }
        }
    }
    __syncthreads();

    // cross-warp reduction; scale by inv[q]; emit ctx as fp16 d-pair words
    float* red = sm + OFF_KH;
#pragma unroll
    for (int mf = 0; mf < 2; mf++)
#pragma unroll
        for (int nf = 0; nf < 4; nf++) {
            const int d = mf * 16 + g;
            const int q = nf * 8 + 2 * t4;
            float* rw = red + wid * 1056;
            rw[q * 33 + d]           = acc[mf][nf][0];
            rw[(q + 1) * 33 + d]     = acc[mf][nf][1];
            rw[q * 33 + d + 8]       = acc[mf][nf][2];
            rw[(q + 1) * 33 + d + 8] = acc[mf][nf][3];
        }
    __syncthreads();

#pragma unroll
    for (int i = 0; i < 2; i++) {
        const int idx = t + i * 256;          // 0..511 = 32 q x 16 words
        const int q = idx >> 4, wp = idx & 15;
        const int d = 2 * wp;
        float s0 = 0.f, s1 = 0.f;
#pragma unroll
        for (int w = 0; w < 8; w++) {
            s0 += red[w * 1056 + q * 33 + d];
            s1 += red[w * 1056 + q * 33 + d + 1];
        }
        const float iv = siv[q];
        g_cw[wbase + (size_t)(q0 + q) * WR + wp] = cvt_h2(s0 * iv, s1 * iv);
    }
}

// ---------------------------------------------------------------------------
// LayerNorm (unchanged)
// ---------------------------------------------------------------------------
__global__ void ln_kernel(const float* __restrict__ gamma,
                          const float* __restrict__ beta,
                          float* __restrict__ out)
{
    __shared__ float red[8];
    const int row = blockIdx.x, t = threadIdx.x;
    const int w = t >> 5, lane = t & 31;

    float4 v = *((const float4*)(g_x + (size_t)row * HIDC) + t);
    float s = v.x + v.y + v.z + v.w;
#pragma unroll
    for (int o = 16; o > 0; o >>= 1) s += __shfl_xor_sync(0xffffffffu, s, o);
    if (lane == 0) red[w] = s;
    __syncthreads();
    if (t == 0) {
        float tt = 0.f;
#pragma unroll
        for (int i = 0; i < 8; i++) tt += red[i];
        red[0] = tt;
    }
    __syncthreads();
    const float mu = red[0] * (1.f / 1024.f);
    __syncthreads();

    float dx = v.x - mu, dy = v.y - mu, dz = v.z - mu, dw = v.w - mu;
    float sq = dx * dx + dy * dy + dz * dz + dw * dw;
#pragma unroll
    for (int o = 16; o > 0; o >>= 1) sq += __shfl_xor_sync(0xffffffffu, sq, o);
    if (lane == 0) red[w] = sq;
    __syncthreads();
    if (t == 0) {
        float tt = 0.f;
#pragma unroll
        for (int i = 0; i < 8; i++) tt += red[i];
        red[0] = tt;
    }
    __syncthreads();
    const float inv = rsqrtf(red[0] * (1.f / 1024.f) + 1e-12f);

    float4 g  = *((const float4*)gamma + t);
    float4 bt = *((const float4*)beta + t);
    float4 o4;
    o4.x = dx * inv * g.x + bt.x;
    o4.y = dy * inv * g.y + bt.y;
    o4.z = dz * inv * g.z + bt.z;
    o4.w = dw * inv * g.w + bt.w;
    *((float4*)(out + (size_t)row * HIDC) + t) = o4;
}

// ---------------------------------------------------------------------------
// Launch
// ---------------------------------------------------------------------------
extern "C" void kernel_launch(void* const* d_in, const int* in_sizes, int n_in,
                              void* d_out, int out_size)
{
    (void)in_sizes; (void)n_in; (void)out_size;
    const float* hidden = (const float*)d_in[0];
    const float* Wq = (const float*)d_in[1];
    const float* bq = (const float*)d_in[2];
    const float* Wk = (const float*)d_in[3];
    const float* bk = (const float*)d_in[4];
    const float* Wv = (const float*)d_in[5];
    const float* bv = (const float*)d_in[6];
    const float* Wo = (const float*)d_in[7];
    const float* bo = (const float*)d_in[8];
    const float* gamma = (const float*)d_in[9];
    const float* beta  = (const float*)d_in[10];
    const float* dist  = (const float*)d_in[11];

    float* out   = (float*)d_out;
    float* probs = out + (size_t)BATCH * SEQ * HIDC;

    cudaFuncSetAttribute(attn_kernel, cudaFuncAttributeMaxDynamicSharedMemorySize,
                         (int)ATTN_SMEM_BYTES);

    // Prepass: fp32 -> fp16 words (destinations device-resolved via `which`)
    cvt_kernel<<<(MR * HIDC / 4) / 256, 256>>>(hidden, 0);
    cvt_kernel<<<(HIDC * HIDC / 4) / 256, 256>>>(Wq, 1);
    cvt_kernel<<<(HIDC * HIDC / 4) / 256, 256>>>(Wk, 2);
    cvt_kernel<<<(HIDC * HIDC / 4) / 256, 256>>>(Wv, 3);
    cvt_kernel<<<(HIDC * HIDC / 4) / 256, 256>>>(Wo, 4);

    qkv_gemm<<<dim3(8, 32, 3), 256>>>(bq, bk, bv);
    attn_kernel<<<dim3(32, 32, 4), 256, ATTN_SMEM_BYTES>>>(dist, probs);
    o_gemm<<<dim3(8, 32, 1), 256>>>(bo, hidden);
    ln_kernel<<<MR, 256>>>(gamma, beta, out);
}